// round 1
// baseline (speedup 1.0000x reference)
#include <cuda_runtime.h>
#include <math.h>
#include <stdint.h>

// Problem constants (B=2, S=2048 -> T=4096 tokens)
#define TN 4096     // tokens
#define HD 2048     // hidden
#define ID 4096     // intermediate
#define NE 8        // experts
#define NK 2        // top-k

// GEMM tiling
#define BM 128
#define BN 64
#define BK 16
#define MAXSLOT (TN*NK + NE*BM)   // 9216 (tile-aligned padded slot capacity)
#define MAXMT   (MAXSLOT/BM)      // 72 m-tiles worst case

// -------- device scratch (static: allocation-free) --------
static __device__ float g_act[(size_t)MAXSLOT * ID];   // gelu(g)*u activations (151 MB)
static __device__ float g_y[(size_t)MAXSLOT * HD];     // per-slot down-proj output (75 MB)
static __device__ int   g_cnt[NE];
static __device__ int   g_cnt2[NE];
static __device__ int   g_off[NE];
static __device__ int   g_tok_e[TN * NK];
static __device__ float g_tok_w[TN * NK];
static __device__ int   g_tok_slot[TN * NK];
static __device__ int   g_slot_token[MAXSLOT];
static __device__ int   g_tile_e[MAXMT];

__device__ __forceinline__ float gelu_tanh(float v) {
    // jax.nn.gelu(approximate=True)
    float v3 = v * v * v;
    return 0.5f * v * (1.0f + tanhf(0.7978845608028654f * (v + 0.044715f * v3)));
}

// -------- K0: zero counters (graph replays must be self-resetting) --------
__global__ void k_zero() {
    if (threadIdx.x < NE) { g_cnt[threadIdx.x] = 0; g_cnt2[threadIdx.x] = 0; }
}

// -------- K1: router logits + top-2 + softmax weights --------
__global__ void k_router(const float* __restrict__ x, const float* __restrict__ gw,
                         float* __restrict__ out_logits) {
    const int t = blockIdx.x;
    const int tid = threadIdx.x;
    float acc[NE];
#pragma unroll
    for (int e = 0; e < NE; e++) acc[e] = 0.f;
    const float* xr = x + (size_t)t * HD;
    for (int h = tid; h < HD; h += 256) {
        float xv = xr[h];
        const float* g = gw + (size_t)h * NE;
#pragma unroll
        for (int e = 0; e < NE; e++) acc[e] += xv * g[e];
    }
    __shared__ float red[256][NE];
#pragma unroll
    for (int e = 0; e < NE; e++) red[tid][e] = acc[e];
    __syncthreads();
    for (int off = 128; off > 0; off >>= 1) {
        if (tid < off) {
#pragma unroll
            for (int e = 0; e < NE; e++) red[tid][e] += red[tid + off][e];
        }
        __syncthreads();
    }
    if (tid == 0) {
        float l[NE];
#pragma unroll
        for (int e = 0; e < NE; e++) l[e] = red[0][e];
        if (out_logits) {
#pragma unroll
            for (int e = 0; e < NE; e++) out_logits[(size_t)t * NE + e] = l[e];
        }
        // top-2 (lowest index wins ties, matching lax.top_k)
        int e0 = 0;
#pragma unroll
        for (int e = 1; e < NE; e++) if (l[e] > l[e0]) e0 = e;
        int e1 = -1;
        float l1 = -1e30f;
#pragma unroll
        for (int e = 0; e < NE; e++) {
            if (e != e0 && l[e] > l1) { l1 = l[e]; e1 = e; }
        }
        float d = expf(l1 - l[e0]);
        float w0 = 1.f / (1.f + d);
        float w1 = d / (1.f + d);
        g_tok_e[2 * t] = e0; g_tok_e[2 * t + 1] = e1;
        g_tok_w[2 * t] = w0; g_tok_w[2 * t + 1] = w1;
        atomicAdd(&g_cnt[e0], 1);
        atomicAdd(&g_cnt[e1], 1);
    }
}

// -------- K2: tile-aligned offsets + tile->expert map + slot init --------
__global__ void k_offsets() {
    const int tid = threadIdx.x;
    if (tid == 0) {
        int cur = 0, mt = 0;
        for (int e = 0; e < NE; e++) {
            g_off[e] = cur;
            int tiles = (g_cnt[e] + BM - 1) / BM;
            for (int j = 0; j < tiles; j++) g_tile_e[mt++] = e;
            cur += tiles * BM;
        }
        for (; mt < MAXMT; mt++) g_tile_e[mt] = -1;
    }
    for (int i = tid; i < MAXSLOT; i += blockDim.x) g_slot_token[i] = -1;
}

// -------- K3: scatter tokens into per-expert slot lists --------
__global__ void k_scatter() {
    int t = blockIdx.x * blockDim.x + threadIdx.x;
    if (t >= TN) return;
#pragma unroll
    for (int k = 0; k < NK; k++) {
        int e = g_tok_e[2 * t + k];
        int pos = atomicAdd(&g_cnt2[e], 1);
        int slot = g_off[e] + pos;
        g_slot_token[slot] = t;
        g_tok_slot[2 * t + k] = slot;
    }
}

// -------- G1: act[slot, i] = gelu(x @ Wg[e]) * (x @ Wu[e]) --------
// grid: (ID/BN, MAXMT). Block tile BM=128 x BN=64, K=HD, dual accumulator.
__global__ void __launch_bounds__(256, 2)
k_gemm1(const float* __restrict__ x, const float* __restrict__ wg_all,
        const float* __restrict__ wu_all) {
    const int mt = blockIdx.y;
    const int e = g_tile_e[mt];
    if (e < 0) return;
    const int m0 = mt * BM;
    const int n0 = blockIdx.x * BN;
    const int tid = threadIdx.x;
    const int tx = tid & 15, ty = tid >> 4;
    const int tm = ty * 8, tn = tx * 4;

    __shared__ float As[BM][BK + 1];
    __shared__ float Bg[BK][BN];
    __shared__ float Bu[BK][BN];
    __shared__ int stok[BM];

    if (tid < BM) stok[tid] = g_slot_token[m0 + tid];
    __syncthreads();

    float ag[8][4], au[8][4];
#pragma unroll
    for (int i = 0; i < 8; i++)
#pragma unroll
        for (int j = 0; j < 4; j++) { ag[i][j] = 0.f; au[i][j] = 0.f; }

    const int ar = tid >> 1;        // A row 0..127
    const int ak = (tid & 1) * 8;   // k offset 0/8
    const int br = tid >> 4;        // B row 0..15
    const int bc = (tid & 15) * 4;  // B col

    const float* wg = wg_all + (size_t)e * HD * ID;
    const float* wu = wu_all + (size_t)e * HD * ID;
    const int tokA = stok[ar];
    const float* xp_base = (tokA >= 0) ? (x + (size_t)tokA * HD + ak) : nullptr;

    for (int kt = 0; kt < HD; kt += BK) {
        float4 a0, a1;
        if (xp_base) {
            a0 = *(const float4*)(xp_base + kt);
            a1 = *(const float4*)(xp_base + kt + 4);
        } else {
            a0 = make_float4(0.f, 0.f, 0.f, 0.f); a1 = a0;
        }
        As[ar][ak + 0] = a0.x; As[ar][ak + 1] = a0.y; As[ar][ak + 2] = a0.z; As[ar][ak + 3] = a0.w;
        As[ar][ak + 4] = a1.x; As[ar][ak + 5] = a1.y; As[ar][ak + 6] = a1.z; As[ar][ak + 7] = a1.w;

        *(float4*)&Bg[br][bc] = *(const float4*)(wg + (size_t)(kt + br) * ID + n0 + bc);
        *(float4*)&Bu[br][bc] = *(const float4*)(wu + (size_t)(kt + br) * ID + n0 + bc);
        __syncthreads();

#pragma unroll
        for (int kk = 0; kk < BK; kk++) {
            float a[8];
#pragma unroll
            for (int i = 0; i < 8; i++) a[i] = As[tm + i][kk];
            float4 bgv = *(float4*)&Bg[kk][tn];
            float4 buv = *(float4*)&Bu[kk][tn];
#pragma unroll
            for (int i = 0; i < 8; i++) {
                ag[i][0] += a[i] * bgv.x; ag[i][1] += a[i] * bgv.y;
                ag[i][2] += a[i] * bgv.z; ag[i][3] += a[i] * bgv.w;
                au[i][0] += a[i] * buv.x; au[i][1] += a[i] * buv.y;
                au[i][2] += a[i] * buv.z; au[i][3] += a[i] * buv.w;
            }
        }
        __syncthreads();
    }

#pragma unroll
    for (int i = 0; i < 8; i++) {
        float4 v;
        v.x = gelu_tanh(ag[i][0]) * au[i][0];
        v.y = gelu_tanh(ag[i][1]) * au[i][1];
        v.z = gelu_tanh(ag[i][2]) * au[i][2];
        v.w = gelu_tanh(ag[i][3]) * au[i][3];
        *(float4*)&g_act[(size_t)(m0 + tm + i) * ID + n0 + tn] = v;
    }
}

// -------- G2: y[slot, h] = act[slot, :] @ down[e] --------
// grid: (HD/BN, MAXMT). K=ID.
__global__ void __launch_bounds__(256, 2)
k_gemm2(const float* __restrict__ wd_all) {
    const int mt = blockIdx.y;
    const int e = g_tile_e[mt];
    if (e < 0) return;
    const int m0 = mt * BM;
    const int n0 = blockIdx.x * BN;
    const int tid = threadIdx.x;
    const int tx = tid & 15, ty = tid >> 4;
    const int tm = ty * 8, tn = tx * 4;

    __shared__ float As[BM][BK + 1];
    __shared__ float Bd[BK][BN];

    float acc[8][4];
#pragma unroll
    for (int i = 0; i < 8; i++)
#pragma unroll
        for (int j = 0; j < 4; j++) acc[i][j] = 0.f;

    const int ar = tid >> 1;
    const int ak = (tid & 1) * 8;
    const int br = tid >> 4;
    const int bc = (tid & 15) * 4;

    const float* wd = wd_all + (size_t)e * ID * HD;
    const float* ap_base = &g_act[(size_t)(m0 + ar) * ID + ak];

    for (int kt = 0; kt < ID; kt += BK) {
        float4 a0 = *(const float4*)(ap_base + kt);
        float4 a1 = *(const float4*)(ap_base + kt + 4);
        As[ar][ak + 0] = a0.x; As[ar][ak + 1] = a0.y; As[ar][ak + 2] = a0.z; As[ar][ak + 3] = a0.w;
        As[ar][ak + 4] = a1.x; As[ar][ak + 5] = a1.y; As[ar][ak + 6] = a1.z; As[ar][ak + 7] = a1.w;

        *(float4*)&Bd[br][bc] = *(const float4*)(wd + (size_t)(kt + br) * HD + n0 + bc);
        __syncthreads();

#pragma unroll
        for (int kk = 0; kk < BK; kk++) {
            float a[8];
#pragma unroll
            for (int i = 0; i < 8; i++) a[i] = As[tm + i][kk];
            float4 bv = *(float4*)&Bd[kk][tn];
#pragma unroll
            for (int i = 0; i < 8; i++) {
                acc[i][0] += a[i] * bv.x; acc[i][1] += a[i] * bv.y;
                acc[i][2] += a[i] * bv.z; acc[i][3] += a[i] * bv.w;
            }
        }
        __syncthreads();
    }

#pragma unroll
    for (int i = 0; i < 8; i++) {
        float4 v = make_float4(acc[i][0], acc[i][1], acc[i][2], acc[i][3]);
        *(float4*)&g_y[(size_t)(m0 + tm + i) * HD + n0 + tn] = v;
    }
}

// -------- K4: combine: out[t,h] = w0*y[s0,h] + w1*y[s1,h] (deterministic, no atomics) --------
__global__ void k_combine(float* __restrict__ out) {
    int idx = blockIdx.x * blockDim.x + threadIdx.x;   // over TN*HD/4
    int t = idx / (HD / 4);
    int c = (idx % (HD / 4)) * 4;
    int s0 = g_tok_slot[2 * t], s1 = g_tok_slot[2 * t + 1];
    float w0 = g_tok_w[2 * t], w1 = g_tok_w[2 * t + 1];
    float4 y0 = *(const float4*)&g_y[(size_t)s0 * HD + c];
    float4 y1 = *(const float4*)&g_y[(size_t)s1 * HD + c];
    float4 r;
    r.x = w0 * y0.x + w1 * y1.x;
    r.y = w0 * y0.y + w1 * y1.y;
    r.z = w0 * y0.z + w1 * y1.z;
    r.w = w0 * y0.w + w1 * y1.w;
    *(float4*)&out[(size_t)t * HD + c] = r;
}

extern "C" void kernel_launch(void* const* d_in, const int* in_sizes, int n_in,
                              void* d_out, int out_size) {
    const float* x  = (const float*)d_in[0];   // [B,S,H]
    const float* gw = (const float*)d_in[1];   // [H,E]
    const float* wg = (const float*)d_in[2];   // [E,H,I]
    const float* wu = (const float*)d_in[3];   // [E,H,I]
    const float* wd = (const float*)d_in[4];   // [E,I,H]
    float* out = (float*)d_out;

    // Output layout assumption: [final (T*H) | router_logits (T*E)]
    float* logits = nullptr;
    if ((long long)out_size >= (long long)TN * HD + (long long)TN * NE)
        logits = out + (size_t)TN * HD;

    k_zero<<<1, 32>>>();
    k_router<<<TN, 256>>>(x, gw, logits);
    k_offsets<<<1, 256>>>();
    k_scatter<<<TN / 256, 256>>>();
    k_gemm1<<<dim3(ID / BN, MAXMT), 256>>>(x, wg, wu);
    k_gemm2<<<dim3(HD / BN, MAXMT), 256>>>(wd);
    k_combine<<<(TN * HD / 4) / 256, 256>>>(out);
}

// round 3
// speedup vs baseline: 2.2515x; 2.2515x over previous
#include <cuda_runtime.h>
#include <cuda_bf16.h>
#include <math.h>
#include <stdint.h>

// ---------------- problem constants ----------------
#define TN 4096     // tokens (B*S)
#define HD 2048     // hidden
#define ID 4096     // intermediate
#define NE 8        // experts
#define NK 2        // top-k
#define BM 128
#define BN 128
#define BK 64
#define MAXSLOT (TN*NK + NE*BM)   // 9216
#define MAXMT   (MAXSLOT/BM)      // 72
#define STG 3
#define STAGE_BYTES 65536         // Ahi 16K + Alo 16K + Bhi 16K + Blo 16K
#define GEMM_SMEM (STG*STAGE_BYTES) // 192 KB

// ---------------- device scratch (static, allocation-free) ----------------
static __device__ __align__(16) __nv_bfloat16 g_x2 [(size_t)MAXSLOT*2*HD];  // x split [hi|lo]   75 MB
static __device__ __align__(16) __nv_bfloat16 g_wg2[(size_t)NE*ID*2*HD];    // gate W^T split   268 MB
static __device__ __align__(16) __nv_bfloat16 g_wu2[(size_t)NE*ID*2*HD];    // up   W^T split   268 MB
static __device__ __align__(16) __nv_bfloat16 g_wd2[(size_t)NE*HD*2*ID];    // down W^T split   268 MB
static __device__ __align__(16) float g_g  [(size_t)MAXSLOT*ID];            // x@Wg fp32        151 MB
static __device__ __align__(16) float g_u  [(size_t)MAXSLOT*ID];            // x@Wu fp32        151 MB
static __device__ __align__(16) __nv_bfloat16 g_a2 [(size_t)MAXSLOT*2*ID];  // act split        151 MB
static __device__ __align__(16) float g_y  [(size_t)MAXSLOT*HD];            //                   75 MB
static __device__ int   g_cnt[NE];
static __device__ int   g_cnt2[NE];
static __device__ int   g_off[NE];
static __device__ int   g_tok_e[TN*NK];
static __device__ float g_tok_w[TN*NK];
static __device__ int   g_tok_slot[TN*NK];
static __device__ int   g_slot_token[MAXSLOT];
static __device__ int   g_tile_e[MAXMT];

// ---------------- small helpers ----------------
__device__ __forceinline__ uint32_t smem_u32(const void* p) {
    uint32_t a;
    asm("{ .reg .u64 t; cvta.to.shared.u64 t, %1; cvt.u32.u64 %0, t; }" : "=r"(a) : "l"(p));
    return a;
}
__device__ __forceinline__ void cp16(uint32_t dst, const void* src) {
    asm volatile("cp.async.cg.shared.global [%0], [%1], 16;" :: "r"(dst), "l"(src));
}
#define CP_COMMIT() asm volatile("cp.async.commit_group;" ::: "memory")
#define CP_WAIT1()  asm volatile("cp.async.wait_group 1;" ::: "memory")
__device__ __forceinline__ void ldsm4(uint32_t* r, uint32_t addr) {
    asm volatile("ldmatrix.sync.aligned.m8n8.x4.shared.b16 {%0,%1,%2,%3}, [%4];"
        : "=r"(r[0]), "=r"(r[1]), "=r"(r[2]), "=r"(r[3]) : "r"(addr));
}
__device__ __forceinline__ void mma16816(float* d, const uint32_t* a, uint32_t b0, uint32_t b1) {
    asm volatile("mma.sync.aligned.m16n8k16.row.col.f32.bf16.bf16.f32 "
        "{%0,%1,%2,%3}, {%4,%5,%6,%7}, {%8,%9}, {%0,%1,%2,%3};"
        : "+f"(d[0]), "+f"(d[1]), "+f"(d[2]), "+f"(d[3])
        : "r"(a[0]), "r"(a[1]), "r"(a[2]), "r"(a[3]), "r"(b0), "r"(b1));
}
__device__ __forceinline__ float gelu_tanh(float v) {
    float v3 = v * v * v;
    return 0.5f * v * (1.0f + tanhf(0.7978845608028654f * (v + 0.044715f * v3)));
}

// ---------------- routing (validated in round 1) ----------------
__global__ void k_zero() {
    if (threadIdx.x < NE) { g_cnt[threadIdx.x] = 0; g_cnt2[threadIdx.x] = 0; }
}

__global__ void k_router(const float* __restrict__ x, const float* __restrict__ gw,
                         float* __restrict__ out_logits) {
    const int t = blockIdx.x;
    const int tid = threadIdx.x;
    float acc[NE];
#pragma unroll
    for (int e = 0; e < NE; e++) acc[e] = 0.f;
    const float* xr = x + (size_t)t * HD;
    for (int h = tid; h < HD; h += 256) {
        float xv = xr[h];
        const float* g = gw + (size_t)h * NE;
#pragma unroll
        for (int e = 0; e < NE; e++) acc[e] += xv * g[e];
    }
    __shared__ float red[256][NE];
#pragma unroll
    for (int e = 0; e < NE; e++) red[tid][e] = acc[e];
    __syncthreads();
    for (int off = 128; off > 0; off >>= 1) {
        if (tid < off) {
#pragma unroll
            for (int e = 0; e < NE; e++) red[tid][e] += red[tid + off][e];
        }
        __syncthreads();
    }
    if (tid == 0) {
        float l[NE];
#pragma unroll
        for (int e = 0; e < NE; e++) l[e] = red[0][e];
        if (out_logits) {
#pragma unroll
            for (int e = 0; e < NE; e++) out_logits[(size_t)t * NE + e] = l[e];
        }
        int e0 = 0;
#pragma unroll
        for (int e = 1; e < NE; e++) if (l[e] > l[e0]) e0 = e;
        int e1 = -1; float l1 = -1e30f;
#pragma unroll
        for (int e = 0; e < NE; e++) if (e != e0 && l[e] > l1) { l1 = l[e]; e1 = e; }
        float d = expf(l1 - l[e0]);
        float w0 = 1.f / (1.f + d);
        g_tok_e[2*t] = e0; g_tok_e[2*t+1] = e1;
        g_tok_w[2*t] = w0; g_tok_w[2*t+1] = 1.f - w0;
        atomicAdd(&g_cnt[e0], 1);
        atomicAdd(&g_cnt[e1], 1);
    }
}

__global__ void k_offsets() {
    const int tid = threadIdx.x;
    if (tid == 0) {
        int cur = 0, mt = 0;
        for (int e = 0; e < NE; e++) {
            g_off[e] = cur;
            int tiles = (g_cnt[e] + BM - 1) / BM;
            for (int j = 0; j < tiles; j++) g_tile_e[mt++] = e;
            cur += tiles * BM;
        }
        for (; mt < MAXMT; mt++) g_tile_e[mt] = -1;
    }
    for (int i = tid; i < MAXSLOT; i += blockDim.x) g_slot_token[i] = -1;
}

__global__ void k_scatter() {
    int t = blockIdx.x * blockDim.x + threadIdx.x;
    if (t >= TN) return;
#pragma unroll
    for (int k = 0; k < NK; k++) {
        int e = g_tok_e[2*t + k];
        int pos = atomicAdd(&g_cnt2[e], 1);
        int slot = g_off[e] + pos;
        g_slot_token[slot] = t;
        g_tok_slot[2*t + k] = slot;
    }
}

// ---------------- prep: weight transpose + bf16 split -> [E][N][hi(K)|lo(K)] ----------------
__global__ void k_splitw(const float* __restrict__ src, __nv_bfloat16* __restrict__ dst,
                         int K, int N) {
    __shared__ float s[32][129];
    int e = blockIdx.z;
    int n0 = blockIdx.x * 128, k0 = blockIdx.y * 32;
    const float* sp = src + (size_t)e * K * N;
    for (int idx = threadIdx.x; idx < 32 * 128; idx += 256) {
        int r = idx >> 7, c = idx & 127;
        s[r][c] = sp[(size_t)(k0 + r) * N + n0 + c];
    }
    __syncthreads();
    size_t K2 = 2 * (size_t)K;
    __nv_bfloat16* dp = dst + (size_t)e * N * K2;
    for (int idx = threadIdx.x; idx < 32 * 128; idx += 256) {
        int n = idx >> 5, k = idx & 31;
        float v = s[k][n];
        __nv_bfloat16 h = __float2bfloat16_rn(v);
        __nv_bfloat16 l = __float2bfloat16_rn(v - __bfloat162float(h));
        __nv_bfloat16* row = dp + (size_t)(n0 + n) * K2;
        row[k0 + k] = h;
        row[K + k0 + k] = l;
    }
}

// ---------------- prep: gather x rows per slot + split -> [slot][hi(HD)|lo(HD)] ----------------
__global__ void k_gatherx(const float* __restrict__ x) {
    int slot = blockIdx.x;
    int t = g_slot_token[slot];
    __nv_bfloat16* row = g_x2 + (size_t)slot * 2 * HD;
    for (int k = threadIdx.x; k < HD; k += 256) {
        float v = (t >= 0) ? x[(size_t)t * HD + k] : 0.f;
        __nv_bfloat16 h = __float2bfloat16_rn(v);
        __nv_bfloat16 l = __float2bfloat16_rn(v - __bfloat162float(h));
        row[k] = h; row[HD + k] = l;
    }
}

// ---------------- generic split-bf16 HMMA GEMM ----------------
// C[m0+.., n0+..] = A_split[m][.] * B_split^T[n][.]  with 3-term correction.
// A: [MAXSLOT][2K] bf16 (hi|lo). B: [NE][N][2K] bf16 (hi|lo). C: [MAXSLOT][N] fp32.
// grid = (N/BN, MAXMT), 256 threads, 3-stage cp.async pipeline, 192KB smem.
__global__ void __launch_bounds__(256, 1)
k_gemm(const __nv_bfloat16* __restrict__ A, const __nv_bfloat16* __restrict__ B,
       float* __restrict__ C, int K, int N) {
    const int mt = blockIdx.y;
    const int e = g_tile_e[mt];
    if (e < 0) return;
    const int m0 = mt * BM;
    const int n0 = blockIdx.x * BN;
    extern __shared__ char smraw[];
    const uint32_t sbase = smem_u32(smraw);
    const int tid = threadIdx.x, lane = tid & 31, wid = tid >> 5;
    const int wm = (wid >> 2) * 64, wn = (wid & 3) * 32;
    const int Kc = K / BK;
    const size_t strA = 2 * (size_t)K;

    // cp.async piece mapping: 1024 16B pieces per 16KB buffer; thread does 4.
    const int prow = tid >> 3, pkc = tid & 7;
    const __nv_bfloat16* aptr = A + (size_t)(m0 + prow) * strA + pkc * 8;
    const __nv_bfloat16* bptr = B + (size_t)e * N * strA + (size_t)(n0 + prow) * strA + pkc * 8;
    const uint32_t soff0 = prow * 128 + ((pkc ^ (prow & 7)) << 4);

    auto load_stage = [&](int s, int c) {
        uint32_t d = sbase + s * STAGE_BYTES + soff0;
        const __nv_bfloat16* a = aptr + c * BK;
        const __nv_bfloat16* b = bptr + c * BK;
#pragma unroll
        for (int t = 0; t < 4; t++) {
            cp16(d + t*4096,          a + (size_t)t*32*strA);      // A hi
            cp16(d + 16384 + t*4096,  a + K + (size_t)t*32*strA);  // A lo
            cp16(d + 32768 + t*4096,  b + (size_t)t*32*strA);      // B hi
            cp16(d + 49152 + t*4096,  b + K + (size_t)t*32*strA);  // B lo
        }
    };

    load_stage(0, 0); CP_COMMIT();
    load_stage(1, 1); CP_COMMIT();

    float acc[4][4][4];
#pragma unroll
    for (int i = 0; i < 4; i++)
#pragma unroll
        for (int j = 0; j < 4; j++)
#pragma unroll
            for (int q = 0; q < 4; q++) acc[i][j][q] = 0.f;

    const int lrow = lane & 15, lk = lane >> 4;

    for (int c = 0; c < Kc; c++) {
        CP_WAIT1();
        __syncthreads();
        if (c + 2 < Kc) load_stage((c + 2) % STG, c + 2);
        CP_COMMIT();
        const uint32_t sa = sbase + (c % STG) * STAGE_BYTES;
        const uint32_t sb = sa + 32768;
#pragma unroll
        for (int ks = 0; ks < 4; ks++) {
            uint32_t ah[4][4], al[4][4], bh[2][4], bl[2][4];
            const int kc = ks * 2 + lk;
#pragma unroll
            for (int mi = 0; mi < 4; mi++) {
                int row = wm + mi * 16 + lrow;
                uint32_t ad = sa + row * 128 + ((kc ^ (row & 7)) << 4);
                ldsm4(ah[mi], ad);
                ldsm4(al[mi], ad + 16384);
            }
#pragma unroll
            for (int ng = 0; ng < 2; ng++) {
                int row = wn + ng * 16 + lrow;
                uint32_t bd = sb + row * 128 + ((kc ^ (row & 7)) << 4);
                ldsm4(bh[ng], bd);
                ldsm4(bl[ng], bd + 16384);
            }
#pragma unroll
            for (int mi = 0; mi < 4; mi++)
#pragma unroll
                for (int nf = 0; nf < 4; nf++) {
                    const int ng = nf >> 1, p = nf & 1;
                    mma16816(acc[mi][nf], ah[mi], bh[ng][p], bh[ng][p + 2]);
                    mma16816(acc[mi][nf], ah[mi], bl[ng][p], bl[ng][p + 2]);
                    mma16816(acc[mi][nf], al[mi], bh[ng][p], bh[ng][p + 2]);
                }
        }
    }

    // epilogue: fp32 accum fragments -> C
#pragma unroll
    for (int mi = 0; mi < 4; mi++)
#pragma unroll
        for (int nf = 0; nf < 4; nf++) {
            int row = m0 + wm + mi * 16 + (lane >> 2);
            int col = n0 + wn + nf * 8 + (lane & 3) * 2;
            float2* p0 = (float2*)&C[(size_t)row * N + col];
            p0->x = acc[mi][nf][0]; p0->y = acc[mi][nf][1];
            float2* p1 = (float2*)&C[(size_t)(row + 8) * N + col];
            p1->x = acc[mi][nf][2]; p1->y = acc[mi][nf][3];
        }
}

// ---------------- act = gelu(g)*u, re-split to bf16 hi/lo ----------------
__global__ void k_act() {
    int idx = blockIdx.x * blockDim.x + threadIdx.x;   // over MAXSLOT*ID/4
    int slot = idx / (ID / 4);
    int c = (idx % (ID / 4)) * 4;
    const float4 gv = *(const float4*)&g_g[(size_t)slot * ID + c];
    const float4 uv = *(const float4*)&g_u[(size_t)slot * ID + c];
    float a0 = gelu_tanh(gv.x) * uv.x;
    float a1 = gelu_tanh(gv.y) * uv.y;
    float a2 = gelu_tanh(gv.z) * uv.z;
    float a3 = gelu_tanh(gv.w) * uv.w;
    __nv_bfloat16 h0 = __float2bfloat16_rn(a0), h1 = __float2bfloat16_rn(a1);
    __nv_bfloat16 h2 = __float2bfloat16_rn(a2), h3 = __float2bfloat16_rn(a3);
    __nv_bfloat16 l0 = __float2bfloat16_rn(a0 - __bfloat162float(h0));
    __nv_bfloat16 l1 = __float2bfloat16_rn(a1 - __bfloat162float(h1));
    __nv_bfloat16 l2 = __float2bfloat16_rn(a2 - __bfloat162float(h2));
    __nv_bfloat16 l3 = __float2bfloat16_rn(a3 - __bfloat162float(h3));
    __nv_bfloat16* row = g_a2 + (size_t)slot * 2 * ID;
    uint2 hv, lv;
    hv.x = (uint32_t)__bfloat16_as_ushort(h0) | ((uint32_t)__bfloat16_as_ushort(h1) << 16);
    hv.y = (uint32_t)__bfloat16_as_ushort(h2) | ((uint32_t)__bfloat16_as_ushort(h3) << 16);
    lv.x = (uint32_t)__bfloat16_as_ushort(l0) | ((uint32_t)__bfloat16_as_ushort(l1) << 16);
    lv.y = (uint32_t)__bfloat16_as_ushort(l2) | ((uint32_t)__bfloat16_as_ushort(l3) << 16);
    *(uint2*)(row + c) = hv;
    *(uint2*)(row + ID + c) = lv;
}

// ---------------- combine ----------------
__global__ void k_combine(float* __restrict__ out) {
    int idx = blockIdx.x * blockDim.x + threadIdx.x;
    int t = idx / (HD / 4);
    int c = (idx % (HD / 4)) * 4;
    int s0 = g_tok_slot[2*t], s1 = g_tok_slot[2*t+1];
    float w0 = g_tok_w[2*t], w1 = g_tok_w[2*t+1];
    float4 y0 = *(const float4*)&g_y[(size_t)s0 * HD + c];
    float4 y1 = *(const float4*)&g_y[(size_t)s1 * HD + c];
    float4 r;
    r.x = w0*y0.x + w1*y1.x; r.y = w0*y0.y + w1*y1.y;
    r.z = w0*y0.z + w1*y1.z; r.w = w0*y0.w + w1*y1.w;
    *(float4*)&out[(size_t)t * HD + c] = r;
}

// ---------------- host ----------------
extern "C" void kernel_launch(void* const* d_in, const int* in_sizes, int n_in,
                              void* d_out, int out_size) {
    const float* x  = (const float*)d_in[0];
    const float* gw = (const float*)d_in[1];
    const float* wg = (const float*)d_in[2];
    const float* wu = (const float*)d_in[3];
    const float* wd = (const float*)d_in[4];
    float* out = (float*)d_out;

    float* logits = nullptr;
    if ((long long)out_size >= (long long)TN * HD + (long long)TN * NE)
        logits = out + (size_t)TN * HD;

    void *p_wg2, *p_wu2, *p_wd2, *p_x2, *p_a2, *p_g, *p_u, *p_y;
    cudaGetSymbolAddress(&p_wg2, g_wg2);
    cudaGetSymbolAddress(&p_wu2, g_wu2);
    cudaGetSymbolAddress(&p_wd2, g_wd2);
    cudaGetSymbolAddress(&p_x2, g_x2);
    cudaGetSymbolAddress(&p_a2, g_a2);
    cudaGetSymbolAddress(&p_g, g_g);
    cudaGetSymbolAddress(&p_u, g_u);
    cudaGetSymbolAddress(&p_y, g_y);

    cudaFuncSetAttribute(k_gemm, cudaFuncAttributeMaxDynamicSharedMemorySize, GEMM_SMEM);

    k_zero<<<1, 32>>>();
    k_router<<<TN, 256>>>(x, gw, logits);
    k_offsets<<<1, 256>>>();
    k_scatter<<<TN / 256, 256>>>();
    k_gatherx<<<MAXSLOT, 256>>>(x);
    k_splitw<<<dim3(ID/128, HD/32, NE), 256>>>(wg, (__nv_bfloat16*)p_wg2, HD, ID);
    k_splitw<<<dim3(ID/128, HD/32, NE), 256>>>(wu, (__nv_bfloat16*)p_wu2, HD, ID);
    k_splitw<<<dim3(HD/128, ID/32, NE), 256>>>(wd, (__nv_bfloat16*)p_wd2, ID, HD);
    // g = x @ Wg, u = x @ Wu  (split-corrected bf16 HMMA)
    k_gemm<<<dim3(ID/BN, MAXMT), 256, GEMM_SMEM>>>(
        (const __nv_bfloat16*)p_x2, (const __nv_bfloat16*)p_wg2, (float*)p_g, HD, ID);
    k_gemm<<<dim3(ID/BN, MAXMT), 256, GEMM_SMEM>>>(
        (const __nv_bfloat16*)p_x2, (const __nv_bfloat16*)p_wu2, (float*)p_u, HD, ID);
    k_act<<<(MAXSLOT * (ID/4)) / 256, 256>>>();
    // y = act @ Wd
    k_gemm<<<dim3(HD/BN, MAXMT), 256, GEMM_SMEM>>>(
        (const __nv_bfloat16*)p_a2, (const __nv_bfloat16*)p_wd2, (float*)p_y, ID, HD);
    k_combine<<<(TN * HD / 4) / 256, 256>>>(out);
}

// round 4
// speedup vs baseline: 2.2913x; 1.0177x over previous
#include <cuda_runtime.h>
#include <cuda_bf16.h>
#include <math.h>
#include <stdint.h>

// ---------------- problem constants ----------------
#define TN 4096
#define HD 2048
#define ID 4096
#define NE 8
#define NK 2
#define BM 128
#define BN 128
#define BK 64
#define MAXSLOT (TN*NK + NE*BM)   // 9216
#define MAXMT   (MAXSLOT/BM)      // 72
#define STG 3
#define STAGE_BYTES 65536
#define GEMM_SMEM (STG*STAGE_BYTES) // 192 KB

// ---------------- device scratch ----------------
static __device__ __align__(16) __nv_bfloat16 g_x2 [(size_t)MAXSLOT*2*HD];  // x split [hi|lo]
static __device__ __align__(16) __nv_bfloat16 g_wg2[(size_t)NE*ID*2*HD];    // gate W^T split
static __device__ __align__(16) __nv_bfloat16 g_wu2[(size_t)NE*ID*2*HD];    // up   W^T split
static __device__ __align__(16) __nv_bfloat16 g_wd2[(size_t)NE*HD*2*ID];    // down W^T split
static __device__ __align__(16) __nv_bfloat16 g_a2 [(size_t)MAXSLOT*2*ID];  // act split
static __device__ __align__(16) float g_y  [(size_t)MAXSLOT*HD];
static __device__ int   g_cnt[NE];
static __device__ int   g_cnt2[NE];
static __device__ int   g_off[NE];
static __device__ int   g_tok_e[TN*NK];
static __device__ float g_tok_w[TN*NK];
static __device__ int   g_tok_slot[TN*NK];
static __device__ int   g_slot_token[MAXSLOT];
static __device__ int   g_tile_e[MAXMT];

// ---------------- helpers ----------------
__device__ __forceinline__ uint32_t smem_u32(const void* p) {
    uint32_t a;
    asm("{ .reg .u64 t; cvta.to.shared.u64 t, %1; cvt.u32.u64 %0, t; }" : "=r"(a) : "l"(p));
    return a;
}
__device__ __forceinline__ void cp16(uint32_t dst, const void* src) {
    asm volatile("cp.async.cg.shared.global [%0], [%1], 16;" :: "r"(dst), "l"(src));
}
#define CP_COMMIT() asm volatile("cp.async.commit_group;" ::: "memory")
#define CP_WAIT1()  asm volatile("cp.async.wait_group 1;" ::: "memory")
__device__ __forceinline__ void ldsm4(uint32_t* r, uint32_t addr) {
    asm volatile("ldmatrix.sync.aligned.m8n8.x4.shared.b16 {%0,%1,%2,%3}, [%4];"
        : "=r"(r[0]), "=r"(r[1]), "=r"(r[2]), "=r"(r[3]) : "r"(addr));
}
__device__ __forceinline__ void mma16816(float* d, const uint32_t* a, uint32_t b0, uint32_t b1) {
    asm volatile("mma.sync.aligned.m16n8k16.row.col.f32.bf16.bf16.f32 "
        "{%0,%1,%2,%3}, {%4,%5,%6,%7}, {%8,%9}, {%0,%1,%2,%3};"
        : "+f"(d[0]), "+f"(d[1]), "+f"(d[2]), "+f"(d[3])
        : "r"(a[0]), "r"(a[1]), "r"(a[2]), "r"(a[3]), "r"(b0), "r"(b1));
}
__device__ __forceinline__ float gelu_tanh(float v) {
    float v3 = v * v * v;
    return 0.5f * v * (1.0f + tanhf(0.7978845608028654f * (v + 0.044715f * v3)));
}
__device__ __forceinline__ uint32_t packbf2(float a, float b) {
    __nv_bfloat16 ha = __float2bfloat16_rn(a), hb = __float2bfloat16_rn(b);
    return (uint32_t)__bfloat16_as_ushort(ha) | ((uint32_t)__bfloat16_as_ushort(hb) << 16);
}

// ---------------- routing ----------------
__global__ void k_zero() {
    if (threadIdx.x < NE) { g_cnt[threadIdx.x] = 0; g_cnt2[threadIdx.x] = 0; }
}

__global__ void k_router(const float* __restrict__ x, const float* __restrict__ gw,
                         float* __restrict__ out_logits) {
    const int t = blockIdx.x;
    const int tid = threadIdx.x;
    float acc[NE];
#pragma unroll
    for (int e = 0; e < NE; e++) acc[e] = 0.f;
    const float* xr = x + (size_t)t * HD;
    for (int h = tid; h < HD; h += 256) {
        float xv = xr[h];
        const float* g = gw + (size_t)h * NE;
#pragma unroll
        for (int e = 0; e < NE; e++) acc[e] += xv * g[e];
    }
    __shared__ float red[256][NE];
#pragma unroll
    for (int e = 0; e < NE; e++) red[tid][e] = acc[e];
    __syncthreads();
    for (int off = 128; off > 0; off >>= 1) {
        if (tid < off) {
#pragma unroll
            for (int e = 0; e < NE; e++) red[tid][e] += red[tid + off][e];
        }
        __syncthreads();
    }
    if (tid == 0) {
        float l[NE];
#pragma unroll
        for (int e = 0; e < NE; e++) l[e] = red[0][e];
        if (out_logits) {
#pragma unroll
            for (int e = 0; e < NE; e++) out_logits[(size_t)t * NE + e] = l[e];
        }
        int e0 = 0;
#pragma unroll
        for (int e = 1; e < NE; e++) if (l[e] > l[e0]) e0 = e;
        int e1 = -1; float l1 = -1e30f;
#pragma unroll
        for (int e = 0; e < NE; e++) if (e != e0 && l[e] > l1) { l1 = l[e]; e1 = e; }
        float d = expf(l1 - l[e0]);
        float w0 = 1.f / (1.f + d);
        g_tok_e[2*t] = e0; g_tok_e[2*t+1] = e1;
        g_tok_w[2*t] = w0; g_tok_w[2*t+1] = 1.f - w0;
        atomicAdd(&g_cnt[e0], 1);
        atomicAdd(&g_cnt[e1], 1);
    }
}

__global__ void k_offsets() {
    const int tid = threadIdx.x;
    if (tid == 0) {
        int cur = 0, mt = 0;
        for (int e = 0; e < NE; e++) {
            g_off[e] = cur;
            int tiles = (g_cnt[e] + BM - 1) / BM;
            for (int j = 0; j < tiles; j++) g_tile_e[mt++] = e;
            cur += tiles * BM;
        }
        for (; mt < MAXMT; mt++) g_tile_e[mt] = -1;
    }
    for (int i = tid; i < MAXSLOT; i += blockDim.x) g_slot_token[i] = -1;
}

__global__ void k_scatter() {
    int t = blockIdx.x * blockDim.x + threadIdx.x;
    if (t >= TN) return;
#pragma unroll
    for (int k = 0; k < NK; k++) {
        int e = g_tok_e[2*t + k];
        int pos = atomicAdd(&g_cnt2[e], 1);
        int slot = g_off[e] + pos;
        g_slot_token[slot] = t;
        g_tok_slot[2*t + k] = slot;
    }
}

// ---------------- prep: weight transpose + bf16 split -> [E][N][hi(K)|lo(K)] ----------------
__global__ void k_splitw(const float* __restrict__ src, __nv_bfloat16* __restrict__ dst,
                         int K, int N) {
    __shared__ float s[32][129];
    int e = blockIdx.z;
    int n0 = blockIdx.x * 128, k0 = blockIdx.y * 32;
    const float* sp = src + (size_t)e * K * N;
    for (int idx = threadIdx.x; idx < 32 * 128; idx += 256) {
        int r = idx >> 7, c = idx & 127;
        s[r][c] = sp[(size_t)(k0 + r) * N + n0 + c];
    }
    __syncthreads();
    size_t K2 = 2 * (size_t)K;
    __nv_bfloat16* dp = dst + (size_t)e * N * K2;
    for (int idx = threadIdx.x; idx < 2048; idx += 256) {
        int n = idx >> 4, kp = (idx & 15) << 1;
        float v0 = s[kp][n], v1 = s[kp + 1][n];
        __nv_bfloat16 h0 = __float2bfloat16_rn(v0), h1 = __float2bfloat16_rn(v1);
        float l0 = v0 - __bfloat162float(h0), l1 = v1 - __bfloat162float(h1);
        __nv_bfloat16* row = dp + (size_t)(n0 + n) * K2;
        *(uint32_t*)&row[k0 + kp] = (uint32_t)__bfloat16_as_ushort(h0) |
                                    ((uint32_t)__bfloat16_as_ushort(h1) << 16);
        *(uint32_t*)&row[K + k0 + kp] = packbf2(l0, l1);
    }
}

// ---------------- prep: gather x rows per slot + split ----------------
__global__ void k_gatherx(const float* __restrict__ x) {
    int slot = blockIdx.x;
    int t = g_slot_token[slot];
    __nv_bfloat16* row = g_x2 + (size_t)slot * 2 * HD;
    for (int k = threadIdx.x * 2; k < HD; k += 512) {
        float v0 = 0.f, v1 = 0.f;
        if (t >= 0) {
            v0 = x[(size_t)t * HD + k];
            v1 = x[(size_t)t * HD + k + 1];
        }
        __nv_bfloat16 h0 = __float2bfloat16_rn(v0), h1 = __float2bfloat16_rn(v1);
        *(uint32_t*)&row[k] = (uint32_t)__bfloat16_as_ushort(h0) |
                              ((uint32_t)__bfloat16_as_ushort(h1) << 16);
        *(uint32_t*)&row[HD + k] = packbf2(v0 - __bfloat162float(h0), v1 - __bfloat162float(h1));
    }
}

// ---------------- GEMM1 fused: g = x@Wg, u = x@Wu, act = gelu(g)*u -> split bf16 ----------------
// grid (MAXMT, ID/64). Stage 64KB: Ahi 16K | Alo 16K | Bg hi 8K | Bg lo 8K | Bu hi 8K | Bu lo 8K
__global__ void __launch_bounds__(256, 1)
k_gemm1f(const __nv_bfloat16* __restrict__ A, const __nv_bfloat16* __restrict__ Bg,
         const __nv_bfloat16* __restrict__ Bu) {
    const int mt = blockIdx.x;
    const int e = g_tile_e[mt];
    if (e < 0) return;
    const int m0 = mt * BM;
    const int n0 = blockIdx.y * 64;
    extern __shared__ char smraw[];
    const uint32_t sbase = smem_u32(smraw);
    const int tid = threadIdx.x, lane = tid & 31, wid = tid >> 5;
    const int w2 = wid & 3;
    const int wm = (w2 >> 1) * 64, wn = (w2 & 1) * 32;
    const size_t strA = 2 * (size_t)HD;
    const int Kc = HD / BK;

    const int prow = tid >> 3, pkc = tid & 7;
    const uint32_t sw = ((uint32_t)(pkc ^ (prow & 7))) << 4;
    const __nv_bfloat16* aptr = A + (size_t)(m0 + prow) * strA + pkc * 8;
    const __nv_bfloat16* bgp = Bg + ((size_t)e * ID + n0 + prow) * strA + pkc * 8;
    const __nv_bfloat16* bup = Bu + ((size_t)e * ID + n0 + prow) * strA + pkc * 8;

    auto load_stage = [&](int s, int c) {
        uint32_t d = sbase + s * STAGE_BYTES;
        const __nv_bfloat16* a = aptr + c * BK;
        const __nv_bfloat16* bg = bgp + c * BK;
        const __nv_bfloat16* bu = bup + c * BK;
#pragma unroll
        for (int t = 0; t < 4; t++) {
            uint32_t dd = d + (prow + 32*t) * 128 + sw;
            cp16(dd,         a + (size_t)(32*t) * strA);
            cp16(dd + 16384, a + (size_t)(32*t) * strA + HD);
        }
#pragma unroll
        for (int t = 0; t < 2; t++) {
            uint32_t dd = d + 32768 + (prow + 32*t) * 128 + sw;
            cp16(dd,          bg + (size_t)(32*t) * strA);
            cp16(dd + 8192,   bg + (size_t)(32*t) * strA + HD);
            cp16(dd + 16384,  bu + (size_t)(32*t) * strA);
            cp16(dd + 24576,  bu + (size_t)(32*t) * strA + HD);
        }
    };

    load_stage(0, 0); CP_COMMIT();
    load_stage(1, 1); CP_COMMIT();

    float acc[4][4][4];
#pragma unroll
    for (int i = 0; i < 4; i++)
#pragma unroll
        for (int j = 0; j < 4; j++)
#pragma unroll
            for (int q = 0; q < 4; q++) acc[i][j][q] = 0.f;

    const int lrow = lane & 15, lk = lane >> 4;
    const uint32_t bsel = (wid >= 4) ? 16384u : 0u;

    for (int c = 0; c < Kc; c++) {
        CP_WAIT1();
        __syncthreads();
        if (c + 2 < Kc) load_stage((c + 2) % STG, c + 2);
        CP_COMMIT();
        const uint32_t sa = sbase + (c % STG) * STAGE_BYTES;
        const uint32_t sb = sa + 32768 + bsel;
#pragma unroll
        for (int ks = 0; ks < 4; ks++) {
            uint32_t ah[4][4], al[4][4], bh[2][4], bl[2][4];
            const int kc = ks * 2 + lk;
#pragma unroll
            for (int mi = 0; mi < 4; mi++) {
                int row = wm + mi * 16 + lrow;
                uint32_t ad = sa + row * 128 + ((kc ^ (row & 7)) << 4);
                ldsm4(ah[mi], ad);
                ldsm4(al[mi], ad + 16384);
            }
#pragma unroll
            for (int ng = 0; ng < 2; ng++) {
                int row = wn + ng * 16 + lrow;
                uint32_t bd = sb + row * 128 + ((kc ^ (row & 7)) << 4);
                ldsm4(bh[ng], bd);
                ldsm4(bl[ng], bd + 8192);
            }
#pragma unroll
            for (int mi = 0; mi < 4; mi++)
#pragma unroll
                for (int nf = 0; nf < 4; nf++) {
                    const int ng = nf >> 1, p = nf & 1;
                    mma16816(acc[mi][nf], ah[mi], bh[ng][p], bh[ng][p + 2]);
                    mma16816(acc[mi][nf], ah[mi], bl[ng][p], bl[ng][p + 2]);
                    mma16816(acc[mi][nf], al[mi], bh[ng][p], bh[ng][p + 2]);
                }
        }
    }

    // epilogue: exchange g/u through smem (pitch 66 floats to dodge bank conflicts)
    __syncthreads();
    float* smf = (float*)smraw;
    float* dstb = smf + (wid < 4 ? 0 : 128 * 66);
#pragma unroll
    for (int mi = 0; mi < 4; mi++)
#pragma unroll
        for (int nf = 0; nf < 4; nf++) {
            int row = wm + mi * 16 + (lane >> 2);
            int col = wn + nf * 8 + (lane & 3) * 2;
            dstb[row * 66 + col]     = acc[mi][nf][0];
            dstb[row * 66 + col + 1] = acc[mi][nf][1];
            dstb[(row + 8) * 66 + col]     = acc[mi][nf][2];
            dstb[(row + 8) * 66 + col + 1] = acc[mi][nf][3];
        }
    __syncthreads();

#pragma unroll
    for (int i = 0; i < 16; i++) {
        int lin = tid + i * 256;        // 0..4095
        int row = lin >> 5;             // 0..127
        int cp = (lin & 31) << 1;       // 0..62
        float g0 = smf[row * 66 + cp],           g1 = smf[row * 66 + cp + 1];
        float u0 = smf[128 * 66 + row * 66 + cp], u1 = smf[128 * 66 + row * 66 + cp + 1];
        float a0 = gelu_tanh(g0) * u0;
        float a1 = gelu_tanh(g1) * u1;
        __nv_bfloat16 h0 = __float2bfloat16_rn(a0), h1 = __float2bfloat16_rn(a1);
        uint32_t hv = (uint32_t)__bfloat16_as_ushort(h0) | ((uint32_t)__bfloat16_as_ushort(h1) << 16);
        uint32_t lv = packbf2(a0 - __bfloat162float(h0), a1 - __bfloat162float(h1));
        __nv_bfloat16* dst = g_a2 + (size_t)(m0 + row) * 2 * ID + n0 + cp;
        *(uint32_t*)dst = hv;
        *(uint32_t*)(dst + ID) = lv;
    }
}

// ---------------- GEMM2: y = act @ Wd (generic split-bf16, grid x=mtile) ----------------
__global__ void __launch_bounds__(256, 1)
k_gemm(const __nv_bfloat16* __restrict__ A, const __nv_bfloat16* __restrict__ B,
       float* __restrict__ C, int K, int N) {
    const int mt = blockIdx.x;
    const int e = g_tile_e[mt];
    if (e < 0) return;
    const int m0 = mt * BM;
    const int n0 = blockIdx.y * BN;
    extern __shared__ char smraw[];
    const uint32_t sbase = smem_u32(smraw);
    const int tid = threadIdx.x, lane = tid & 31, wid = tid >> 5;
    const int wm = (wid >> 2) * 64, wn = (wid & 3) * 32;
    const int Kc = K / BK;
    const size_t strA = 2 * (size_t)K;

    const int prow = tid >> 3, pkc = tid & 7;
    const __nv_bfloat16* aptr = A + (size_t)(m0 + prow) * strA + pkc * 8;
    const __nv_bfloat16* bptr = B + (size_t)e * N * strA + (size_t)(n0 + prow) * strA + pkc * 8;
    const uint32_t soff0 = prow * 128 + ((pkc ^ (prow & 7)) << 4);

    auto load_stage = [&](int s, int c) {
        uint32_t d = sbase + s * STAGE_BYTES + soff0;
        const __nv_bfloat16* a = aptr + c * BK;
        const __nv_bfloat16* b = bptr + c * BK;
#pragma unroll
        for (int t = 0; t < 4; t++) {
            cp16(d + t*4096,          a + (size_t)t*32*strA);
            cp16(d + 16384 + t*4096,  a + K + (size_t)t*32*strA);
            cp16(d + 32768 + t*4096,  b + (size_t)t*32*strA);
            cp16(d + 49152 + t*4096,  b + K + (size_t)t*32*strA);
        }
    };

    load_stage(0, 0); CP_COMMIT();
    load_stage(1, 1); CP_COMMIT();

    float acc[4][4][4];
#pragma unroll
    for (int i = 0; i < 4; i++)
#pragma unroll
        for (int j = 0; j < 4; j++)
#pragma unroll
            for (int q = 0; q < 4; q++) acc[i][j][q] = 0.f;

    const int lrow = lane & 15, lk = lane >> 4;

    for (int c = 0; c < Kc; c++) {
        CP_WAIT1();
        __syncthreads();
        if (c + 2 < Kc) load_stage((c + 2) % STG, c + 2);
        CP_COMMIT();
        const uint32_t sa = sbase + (c % STG) * STAGE_BYTES;
        const uint32_t sb = sa + 32768;
#pragma unroll
        for (int ks = 0; ks < 4; ks++) {
            uint32_t ah[4][4], al[4][4], bh[2][4], bl[2][4];
            const int kc = ks * 2 + lk;
#pragma unroll
            for (int mi = 0; mi < 4; mi++) {
                int row = wm + mi * 16 + lrow;
                uint32_t ad = sa + row * 128 + ((kc ^ (row & 7)) << 4);
                ldsm4(ah[mi], ad);
                ldsm4(al[mi], ad + 16384);
            }
#pragma unroll
            for (int ng = 0; ng < 2; ng++) {
                int row = wn + ng * 16 + lrow;
                uint32_t bd = sb + row * 128 + ((kc ^ (row & 7)) << 4);
                ldsm4(bh[ng], bd);
                ldsm4(bl[ng], bd + 16384);
            }
#pragma unroll
            for (int mi = 0; mi < 4; mi++)
#pragma unroll
                for (int nf = 0; nf < 4; nf++) {
                    const int ng = nf >> 1, p = nf & 1;
                    mma16816(acc[mi][nf], ah[mi], bh[ng][p], bh[ng][p + 2]);
                    mma16816(acc[mi][nf], ah[mi], bl[ng][p], bl[ng][p + 2]);
                    mma16816(acc[mi][nf], al[mi], bh[ng][p], bh[ng][p + 2]);
                }
        }
    }

#pragma unroll
    for (int mi = 0; mi < 4; mi++)
#pragma unroll
        for (int nf = 0; nf < 4; nf++) {
            int row = m0 + wm + mi * 16 + (lane >> 2);
            int col = n0 + wn + nf * 8 + (lane & 3) * 2;
            float2* p0 = (float2*)&C[(size_t)row * N + col];
            p0->x = acc[mi][nf][0]; p0->y = acc[mi][nf][1];
            float2* p1 = (float2*)&C[(size_t)(row + 8) * N + col];
            p1->x = acc[mi][nf][2]; p1->y = acc[mi][nf][3];
        }
}

// ---------------- combine ----------------
__global__ void k_combine(float* __restrict__ out) {
    int idx = blockIdx.x * blockDim.x + threadIdx.x;
    int t = idx / (HD / 4);
    int c = (idx % (HD / 4)) * 4;
    int s0 = g_tok_slot[2*t], s1 = g_tok_slot[2*t+1];
    float w0 = g_tok_w[2*t], w1 = g_tok_w[2*t+1];
    float4 y0 = *(const float4*)&g_y[(size_t)s0 * HD + c];
    float4 y1 = *(const float4*)&g_y[(size_t)s1 * HD + c];
    float4 r;
    r.x = w0*y0.x + w1*y1.x; r.y = w0*y0.y + w1*y1.y;
    r.z = w0*y0.z + w1*y1.z; r.w = w0*y0.w + w1*y1.w;
    *(float4*)&out[(size_t)t * HD + c] = r;
}

// ---------------- host ----------------
extern "C" void kernel_launch(void* const* d_in, const int* in_sizes, int n_in,
                              void* d_out, int out_size) {
    const float* x  = (const float*)d_in[0];
    const float* gw = (const float*)d_in[1];
    const float* wg = (const float*)d_in[2];
    const float* wu = (const float*)d_in[3];
    const float* wd = (const float*)d_in[4];
    float* out = (float*)d_out;

    float* logits = nullptr;
    if ((long long)out_size >= (long long)TN * HD + (long long)TN * NE)
        logits = out + (size_t)TN * HD;

    void *p_wg2, *p_wu2, *p_wd2, *p_x2, *p_a2, *p_y;
    cudaGetSymbolAddress(&p_wg2, g_wg2);
    cudaGetSymbolAddress(&p_wu2, g_wu2);
    cudaGetSymbolAddress(&p_wd2, g_wd2);
    cudaGetSymbolAddress(&p_x2, g_x2);
    cudaGetSymbolAddress(&p_a2, g_a2);
    cudaGetSymbolAddress(&p_y, g_y);

    cudaFuncSetAttribute(k_gemm1f, cudaFuncAttributeMaxDynamicSharedMemorySize, GEMM_SMEM);
    cudaFuncSetAttribute(k_gemm,   cudaFuncAttributeMaxDynamicSharedMemorySize, GEMM_SMEM);

    k_zero<<<1, 32>>>();
    k_router<<<TN, 256>>>(x, gw, logits);
    k_offsets<<<1, 256>>>();
    k_scatter<<<TN / 256, 256>>>();
    k_gatherx<<<MAXSLOT, 256>>>(x);
    k_splitw<<<dim3(ID/128, HD/32, NE), 256>>>(wg, (__nv_bfloat16*)p_wg2, HD, ID);
    k_splitw<<<dim3(ID/128, HD/32, NE), 256>>>(wu, (__nv_bfloat16*)p_wu2, HD, ID);
    k_splitw<<<dim3(HD/128, ID/32, NE), 256>>>(wd, (__nv_bfloat16*)p_wd2, ID, HD);
    k_gemm1f<<<dim3(MAXMT, ID/64), 256, GEMM_SMEM>>>(
        (const __nv_bfloat16*)p_x2, (const __nv_bfloat16*)p_wg2, (const __nv_bfloat16*)p_wu2);
    k_gemm<<<dim3(MAXMT, HD/BN), 256, GEMM_SMEM>>>(
        (const __nv_bfloat16*)p_a2, (const __nv_bfloat16*)p_wd2, (float*)p_y, ID, HD);
    k_combine<<<(TN * HD / 4) / 256, 256>>>(out);
}

// round 5
// speedup vs baseline: 3.3832x; 1.4765x over previous
#include <cuda_runtime.h>
#include <cuda_fp16.h>
#include <math.h>
#include <stdint.h>

// ---------------- problem constants ----------------
#define TN 4096
#define HD 2048
#define ID 4096
#define NE 8
#define NK 2
#define BM 128
#define BN 128
#define BK 64
#define MAXSLOT (TN*NK + NE*BM)   // 9216
#define MAXMT   (MAXSLOT/BM)      // 72
#define STAGE1 65536              // GEMM1: Ahi 16K | Alo 16K | Bg 16K | Bu 16K
#define STAGE2 49152              // GEMM2: Ahi 16K | Alo 16K | B 16K
#define G1_SMEM (3*STAGE1)        // 192 KB
#define G2_SMEM (4*STAGE2)        // 192 KB

// ---------------- device scratch ----------------
static __device__ __align__(16) __half g_x2 [(size_t)MAXSLOT*2*HD];  // x split [hi|lo] fp16
static __device__ __align__(16) __half g_wg [(size_t)NE*ID*HD];      // gate W^T fp16
static __device__ __align__(16) __half g_wu [(size_t)NE*ID*HD];      // up   W^T fp16
static __device__ __align__(16) __half g_wd [(size_t)NE*HD*ID];      // down W^T fp16
static __device__ __align__(16) __half g_a2 [(size_t)MAXSLOT*2*ID];  // act split [hi|lo] fp16
static __device__ __align__(16) float g_y  [(size_t)MAXSLOT*HD];
static __device__ int   g_cnt[NE];
static __device__ int   g_cnt2[NE];
static __device__ int   g_off[NE];
static __device__ int   g_tok_e[TN*NK];
static __device__ float g_tok_w[TN*NK];
static __device__ int   g_tok_slot[TN*NK];
static __device__ int   g_slot_token[MAXSLOT];
static __device__ int   g_tile_e[MAXMT];

// ---------------- helpers ----------------
__device__ __forceinline__ uint32_t smem_u32(const void* p) {
    uint32_t a;
    asm("{ .reg .u64 t; cvta.to.shared.u64 t, %1; cvt.u32.u64 %0, t; }" : "=r"(a) : "l"(p));
    return a;
}
__device__ __forceinline__ void cp16(uint32_t dst, const void* src) {
    asm volatile("cp.async.cg.shared.global [%0], [%1], 16;" :: "r"(dst), "l"(src));
}
#define CP_COMMIT() asm volatile("cp.async.commit_group;" ::: "memory")
#define CP_WAIT1()  asm volatile("cp.async.wait_group 1;" ::: "memory")
#define CP_WAIT2()  asm volatile("cp.async.wait_group 2;" ::: "memory")
__device__ __forceinline__ void ldsm4(uint32_t* r, uint32_t addr) {
    asm volatile("ldmatrix.sync.aligned.m8n8.x4.shared.b16 {%0,%1,%2,%3}, [%4];"
        : "=r"(r[0]), "=r"(r[1]), "=r"(r[2]), "=r"(r[3]) : "r"(addr));
}
__device__ __forceinline__ void mmah(float* d, const uint32_t* a, uint32_t b0, uint32_t b1) {
    asm volatile("mma.sync.aligned.m16n8k16.row.col.f32.f16.f16.f32 "
        "{%0,%1,%2,%3}, {%4,%5,%6,%7}, {%8,%9}, {%0,%1,%2,%3};"
        : "+f"(d[0]), "+f"(d[1]), "+f"(d[2]), "+f"(d[3])
        : "r"(a[0]), "r"(a[1]), "r"(a[2]), "r"(a[3]), "r"(b0), "r"(b1));
}
__device__ __forceinline__ float gelu_tanh(float v) {
    float v3 = v * v * v;
    return 0.5f * v * (1.0f + tanhf(0.7978845608028654f * (v + 0.044715f * v3)));
}
__device__ __forceinline__ uint32_t packh2(float a, float b) {
    __half ha = __float2half_rn(a), hb = __float2half_rn(b);
    return (uint32_t)__half_as_ushort(ha) | ((uint32_t)__half_as_ushort(hb) << 16);
}

// ---------------- routing ----------------
__global__ void k_zero() {
    if (threadIdx.x < NE) { g_cnt[threadIdx.x] = 0; g_cnt2[threadIdx.x] = 0; }
}

__global__ void k_router(const float* __restrict__ x, const float* __restrict__ gw,
                         float* __restrict__ out_logits) {
    const int t = blockIdx.x;
    const int tid = threadIdx.x;
    float acc[NE];
#pragma unroll
    for (int e = 0; e < NE; e++) acc[e] = 0.f;
    const float* xr = x + (size_t)t * HD;
    for (int h = tid; h < HD; h += 256) {
        float xv = xr[h];
        const float* g = gw + (size_t)h * NE;
#pragma unroll
        for (int e = 0; e < NE; e++) acc[e] += xv * g[e];
    }
    __shared__ float red[256][NE];
#pragma unroll
    for (int e = 0; e < NE; e++) red[tid][e] = acc[e];
    __syncthreads();
    for (int off = 128; off > 0; off >>= 1) {
        if (tid < off) {
#pragma unroll
            for (int e = 0; e < NE; e++) red[tid][e] += red[tid + off][e];
        }
        __syncthreads();
    }
    if (tid == 0) {
        float l[NE];
#pragma unroll
        for (int e = 0; e < NE; e++) l[e] = red[0][e];
        if (out_logits) {
#pragma unroll
            for (int e = 0; e < NE; e++) out_logits[(size_t)t * NE + e] = l[e];
        }
        int e0 = 0;
#pragma unroll
        for (int e = 1; e < NE; e++) if (l[e] > l[e0]) e0 = e;
        int e1 = -1; float l1 = -1e30f;
#pragma unroll
        for (int e = 0; e < NE; e++) if (e != e0 && l[e] > l1) { l1 = l[e]; e1 = e; }
        float d = expf(l1 - l[e0]);
        float w0 = 1.f / (1.f + d);
        g_tok_e[2*t] = e0; g_tok_e[2*t+1] = e1;
        g_tok_w[2*t] = w0; g_tok_w[2*t+1] = 1.f - w0;
        atomicAdd(&g_cnt[e0], 1);
        atomicAdd(&g_cnt[e1], 1);
    }
}

__global__ void k_offsets() {
    const int tid = threadIdx.x;
    if (tid == 0) {
        int cur = 0, mt = 0;
        for (int e = 0; e < NE; e++) {
            g_off[e] = cur;
            int tiles = (g_cnt[e] + BM - 1) / BM;
            for (int j = 0; j < tiles; j++) g_tile_e[mt++] = e;
            cur += tiles * BM;
        }
        for (; mt < MAXMT; mt++) g_tile_e[mt] = -1;
    }
    for (int i = tid; i < MAXSLOT; i += blockDim.x) g_slot_token[i] = -1;
}

__global__ void k_scatter() {
    int t = blockIdx.x * blockDim.x + threadIdx.x;
    if (t >= TN) return;
#pragma unroll
    for (int k = 0; k < NK; k++) {
        int e = g_tok_e[2*t + k];
        int pos = atomicAdd(&g_cnt2[e], 1);
        int slot = g_off[e] + pos;
        g_slot_token[slot] = t;
        g_tok_slot[2*t + k] = slot;
    }
}

// ---------------- prep: weight transpose + fp16 convert -> [E][N][K] ----------------
__global__ void k_prepw(const float* __restrict__ src, __half* __restrict__ dst,
                        int K, int N) {
    __shared__ float s[32][129];
    int e = blockIdx.z;
    int n0 = blockIdx.x * 128, k0 = blockIdx.y * 32;
    const float* sp = src + (size_t)e * K * N;
    for (int idx = threadIdx.x; idx < 32 * 128; idx += 256) {
        int r = idx >> 7, c = idx & 127;
        s[r][c] = sp[(size_t)(k0 + r) * N + n0 + c];
    }
    __syncthreads();
    __half* dp = dst + (size_t)e * N * K;
    for (int idx = threadIdx.x; idx < 2048; idx += 256) {
        int n = idx >> 4, kp = (idx & 15) << 1;
        *(uint32_t*)&dp[(size_t)(n0 + n) * K + k0 + kp] = packh2(s[kp][n], s[kp + 1][n]);
    }
}

// ---------------- prep: gather x rows per slot + fp16 split -> [slot][hi(HD)|lo(HD)] ----------------
__global__ void k_gatherx(const float* __restrict__ x) {
    int slot = blockIdx.x;
    int t = g_slot_token[slot];
    __half* row = g_x2 + (size_t)slot * 2 * HD;
    for (int k = threadIdx.x * 2; k < HD; k += 512) {
        float v0 = 0.f, v1 = 0.f;
        if (t >= 0) {
            v0 = x[(size_t)t * HD + k];
            v1 = x[(size_t)t * HD + k + 1];
        }
        __half h0 = __float2half_rn(v0), h1 = __float2half_rn(v1);
        *(uint32_t*)&row[k] = (uint32_t)__half_as_ushort(h0) |
                              ((uint32_t)__half_as_ushort(h1) << 16);
        *(uint32_t*)&row[HD + k] = packh2(v0 - __half2float(h0), v1 - __half2float(h1));
    }
}

// ---------------- GEMM1 fused: g = x@Wg, u = x@Wu, act = gelu(g)*u -> split fp16 ----------------
// grid (MAXMT, ID/128), 256 thr, 3-stage. Stage: Ahi 16K | Alo 16K | Bg 16K | Bu 16K
__global__ void __launch_bounds__(256, 1)
k_gemm1f(const __half* __restrict__ A, const __half* __restrict__ Bg,
         const __half* __restrict__ Bu) {
    const int mt = blockIdx.x;
    const int e = g_tile_e[mt];
    if (e < 0) return;
    const int m0 = mt * BM;
    const int n0 = blockIdx.y * BN;
    extern __shared__ char smraw[];
    const uint32_t sbase = smem_u32(smraw);
    const int tid = threadIdx.x, lane = tid & 31, wid = tid >> 5;
    const int wm = (wid >> 2) * 64, wn = (wid & 3) * 32;
    const size_t strA = 2 * (size_t)HD;
    const int Kc = HD / BK;   // 32

    const int prow = tid >> 3, pkc = tid & 7;
    const uint32_t sw = ((uint32_t)(pkc ^ (prow & 7))) << 4;
    const __half* aptr = A + (size_t)(m0 + prow) * strA + pkc * 8;
    const __half* bgp = Bg + ((size_t)e * ID + n0 + prow) * HD + pkc * 8;
    const __half* bup = Bu + ((size_t)e * ID + n0 + prow) * HD + pkc * 8;

    auto load_stage = [&](int s, int c) {
        uint32_t d = sbase + s * STAGE1;
        const __half* a = aptr + c * BK;
        const __half* bg = bgp + c * BK;
        const __half* bu = bup + c * BK;
#pragma unroll
        for (int t = 0; t < 4; t++) {
            uint32_t dd = d + (prow + 32*t) * 128 + sw;
            cp16(dd,          a  + (size_t)(32*t) * strA);       // A hi
            cp16(dd + 16384,  a  + (size_t)(32*t) * strA + HD);  // A lo
            cp16(dd + 32768,  bg + (size_t)(32*t) * HD);
            cp16(dd + 49152,  bu + (size_t)(32*t) * HD);
        }
    };

    load_stage(0, 0); CP_COMMIT();
    load_stage(1, 1); CP_COMMIT();

    float accg[4][4][4], accu[4][4][4];
#pragma unroll
    for (int i = 0; i < 4; i++)
#pragma unroll
        for (int j = 0; j < 4; j++)
#pragma unroll
            for (int q = 0; q < 4; q++) { accg[i][j][q] = 0.f; accu[i][j][q] = 0.f; }

    const int lrow = lane & 15, lk = lane >> 4;

    for (int c = 0; c < Kc; c++) {
        CP_WAIT1();
        __syncthreads();
        if (c + 2 < Kc) load_stage((c + 2) % 3, c + 2);
        CP_COMMIT();
        const uint32_t sa = sbase + (c % 3) * STAGE1;
#pragma unroll
        for (int ks = 0; ks < 4; ks++) {
            uint32_t ah[4][4], al[4][4], bgf[2][4], buf[2][4];
            const int kc = ks * 2 + lk;
#pragma unroll
            for (int mi = 0; mi < 4; mi++) {
                int row = wm + mi * 16 + lrow;
                uint32_t ad = sa + row * 128 + ((kc ^ (row & 7)) << 4);
                ldsm4(ah[mi], ad);
                ldsm4(al[mi], ad + 16384);
            }
#pragma unroll
            for (int ng = 0; ng < 2; ng++) {
                int row = wn + ng * 16 + lrow;
                uint32_t bd = sa + 32768 + row * 128 + ((kc ^ (row & 7)) << 4);
                ldsm4(bgf[ng], bd);
                ldsm4(buf[ng], bd + 16384);
            }
#pragma unroll
            for (int mi = 0; mi < 4; mi++)
#pragma unroll
                for (int nf = 0; nf < 4; nf++) {
                    const int ng = nf >> 1, p = nf & 1;
                    mmah(accg[mi][nf], ah[mi], bgf[ng][p], bgf[ng][p + 2]);
                    mmah(accg[mi][nf], al[mi], bgf[ng][p], bgf[ng][p + 2]);
                    mmah(accu[mi][nf], ah[mi], buf[ng][p], buf[ng][p + 2]);
                    mmah(accu[mi][nf], al[mi], buf[ng][p], buf[ng][p + 2]);
                }
        }
    }

    // epilogue: gelu(g)*u in registers -> split fp16 hi/lo stores
    const int r0 = lane >> 2, c0 = (lane & 3) * 2;
#pragma unroll
    for (int mi = 0; mi < 4; mi++)
#pragma unroll
        for (int nf = 0; nf < 4; nf++) {
            int grow = m0 + wm + mi * 16 + r0;
            int col = n0 + wn + nf * 8 + c0;
            float a0 = gelu_tanh(accg[mi][nf][0]) * accu[mi][nf][0];
            float a1 = gelu_tanh(accg[mi][nf][1]) * accu[mi][nf][1];
            float a2 = gelu_tanh(accg[mi][nf][2]) * accu[mi][nf][2];
            float a3 = gelu_tanh(accg[mi][nf][3]) * accu[mi][nf][3];
            __half h0 = __float2half_rn(a0), h1 = __float2half_rn(a1);
            __half h2 = __float2half_rn(a2), h3 = __float2half_rn(a3);
            __half* d0 = g_a2 + (size_t)grow * 2 * ID + col;
            __half* d1 = g_a2 + (size_t)(grow + 8) * 2 * ID + col;
            *(uint32_t*)d0 = (uint32_t)__half_as_ushort(h0) | ((uint32_t)__half_as_ushort(h1) << 16);
            *(uint32_t*)(d0 + ID) = packh2(a0 - __half2float(h0), a1 - __half2float(h1));
            *(uint32_t*)d1 = (uint32_t)__half_as_ushort(h2) | ((uint32_t)__half_as_ushort(h3) << 16);
            *(uint32_t*)(d1 + ID) = packh2(a2 - __half2float(h2), a3 - __half2float(h3));
        }
}

// ---------------- GEMM2: y = act @ Wd (A split fp16, B single plane, 4-stage) ----------------
__global__ void __launch_bounds__(256, 1)
k_gemm2(const __half* __restrict__ A, const __half* __restrict__ B,
        float* __restrict__ C) {
    const int mt = blockIdx.x;
    const int e = g_tile_e[mt];
    if (e < 0) return;
    const int m0 = mt * BM;
    const int n0 = blockIdx.y * BN;
    extern __shared__ char smraw[];
    const uint32_t sbase = smem_u32(smraw);
    const int tid = threadIdx.x, lane = tid & 31, wid = tid >> 5;
    const int wm = (wid >> 2) * 64, wn = (wid & 3) * 32;
    const int Kc = ID / BK;   // 64
    const size_t strA = 2 * (size_t)ID;

    const int prow = tid >> 3, pkc = tid & 7;
    const uint32_t sw = ((uint32_t)(pkc ^ (prow & 7))) << 4;
    const __half* aptr = A + (size_t)(m0 + prow) * strA + pkc * 8;
    const __half* bptr = B + ((size_t)e * HD + n0 + prow) * ID + pkc * 8;

    auto load_stage = [&](int s, int c) {
        uint32_t d = sbase + s * STAGE2;
        const __half* a = aptr + c * BK;
        const __half* b = bptr + c * BK;
#pragma unroll
        for (int t = 0; t < 4; t++) {
            uint32_t dd = d + (prow + 32*t) * 128 + sw;
            cp16(dd,          a + (size_t)(32*t) * strA);
            cp16(dd + 16384,  a + (size_t)(32*t) * strA + ID);
            cp16(dd + 32768,  b + (size_t)(32*t) * ID);
        }
    };

    load_stage(0, 0); CP_COMMIT();
    load_stage(1, 1); CP_COMMIT();
    load_stage(2, 2); CP_COMMIT();

    float acc[4][4][4];
#pragma unroll
    for (int i = 0; i < 4; i++)
#pragma unroll
        for (int j = 0; j < 4; j++)
#pragma unroll
            for (int q = 0; q < 4; q++) acc[i][j][q] = 0.f;

    const int lrow = lane & 15, lk = lane >> 4;

    for (int c = 0; c < Kc; c++) {
        CP_WAIT2();
        __syncthreads();
        if (c + 3 < Kc) load_stage((c + 3) & 3, c + 3);
        CP_COMMIT();
        const uint32_t sa = sbase + (c & 3) * STAGE2;
#pragma unroll
        for (int ks = 0; ks < 4; ks++) {
            uint32_t ah[4][4], al[4][4], bf[2][4];
            const int kc = ks * 2 + lk;
#pragma unroll
            for (int mi = 0; mi < 4; mi++) {
                int row = wm + mi * 16 + lrow;
                uint32_t ad = sa + row * 128 + ((kc ^ (row & 7)) << 4);
                ldsm4(ah[mi], ad);
                ldsm4(al[mi], ad + 16384);
            }
#pragma unroll
            for (int ng = 0; ng < 2; ng++) {
                int row = wn + ng * 16 + lrow;
                uint32_t bd = sa + 32768 + row * 128 + ((kc ^ (row & 7)) << 4);
                ldsm4(bf[ng], bd);
            }
#pragma unroll
            for (int mi = 0; mi < 4; mi++)
#pragma unroll
                for (int nf = 0; nf < 4; nf++) {
                    const int ng = nf >> 1, p = nf & 1;
                    mmah(acc[mi][nf], ah[mi], bf[ng][p], bf[ng][p + 2]);
                    mmah(acc[mi][nf], al[mi], bf[ng][p], bf[ng][p + 2]);
                }
        }
    }

#pragma unroll
    for (int mi = 0; mi < 4; mi++)
#pragma unroll
        for (int nf = 0; nf < 4; nf++) {
            int row = m0 + wm + mi * 16 + (lane >> 2);
            int col = n0 + wn + nf * 8 + (lane & 3) * 2;
            float2* p0 = (float2*)&C[(size_t)row * HD + col];
            p0->x = acc[mi][nf][0]; p0->y = acc[mi][nf][1];
            float2* p1 = (float2*)&C[(size_t)(row + 8) * HD + col];
            p1->x = acc[mi][nf][2]; p1->y = acc[mi][nf][3];
        }
}

// ---------------- combine ----------------
__global__ void k_combine(float* __restrict__ out) {
    int idx = blockIdx.x * blockDim.x + threadIdx.x;
    int t = idx / (HD / 4);
    int c = (idx % (HD / 4)) * 4;
    int s0 = g_tok_slot[2*t], s1 = g_tok_slot[2*t+1];
    float w0 = g_tok_w[2*t], w1 = g_tok_w[2*t+1];
    float4 y0 = *(const float4*)&g_y[(size_t)s0 * HD + c];
    float4 y1 = *(const float4*)&g_y[(size_t)s1 * HD + c];
    float4 r;
    r.x = w0*y0.x + w1*y1.x; r.y = w0*y0.y + w1*y1.y;
    r.z = w0*y0.z + w1*y1.z; r.w = w0*y0.w + w1*y1.w;
    *(float4*)&out[(size_t)t * HD + c] = r;
}

// ---------------- host ----------------
extern "C" void kernel_launch(void* const* d_in, const int* in_sizes, int n_in,
                              void* d_out, int out_size) {
    const float* x  = (const float*)d_in[0];
    const float* gw = (const float*)d_in[1];
    const float* wg = (const float*)d_in[2];
    const float* wu = (const float*)d_in[3];
    const float* wd = (const float*)d_in[4];
    float* out = (float*)d_out;

    float* logits = nullptr;
    if ((long long)out_size >= (long long)TN * HD + (long long)TN * NE)
        logits = out + (size_t)TN * HD;

    void *p_wg, *p_wu, *p_wd, *p_x2, *p_a2, *p_y;
    cudaGetSymbolAddress(&p_wg, g_wg);
    cudaGetSymbolAddress(&p_wu, g_wu);
    cudaGetSymbolAddress(&p_wd, g_wd);
    cudaGetSymbolAddress(&p_x2, g_x2);
    cudaGetSymbolAddress(&p_a2, g_a2);
    cudaGetSymbolAddress(&p_y, g_y);

    cudaFuncSetAttribute(k_gemm1f, cudaFuncAttributeMaxDynamicSharedMemorySize, G1_SMEM);
    cudaFuncSetAttribute(k_gemm2,  cudaFuncAttributeMaxDynamicSharedMemorySize, G2_SMEM);

    k_zero<<<1, 32>>>();
    k_router<<<TN, 256>>>(x, gw, logits);
    k_offsets<<<1, 256>>>();
    k_scatter<<<TN / 256, 256>>>();
    k_gatherx<<<MAXSLOT, 256>>>(x);
    k_prepw<<<dim3(ID/128, HD/32, NE), 256>>>(wg, (__half*)p_wg, HD, ID);
    k_prepw<<<dim3(ID/128, HD/32, NE), 256>>>(wu, (__half*)p_wu, HD, ID);
    k_prepw<<<dim3(HD/128, ID/32, NE), 256>>>(wd, (__half*)p_wd, ID, HD);
    k_gemm1f<<<dim3(MAXMT, ID/BN), 256, G1_SMEM>>>(
        (const __half*)p_x2, (const __half*)p_wg, (const __half*)p_wu);
    k_gemm2<<<dim3(MAXMT, HD/BN), 256, G2_SMEM>>>(
        (const __half*)p_a2, (const __half*)p_wd, (float*)p_y);
    k_combine<<<(TN * HD / 4) / 256, 256>>>(out);
}

// round 6
// speedup vs baseline: 5.6098x; 1.6582x over previous
#include <cuda_runtime.h>
#include <cuda_fp16.h>
#include <math.h>
#include <stdint.h>

// ---------------- problem constants ----------------
#define TN 4096
#define HD 2048
#define ID 4096
#define NE 8
#define NK 2
#define BM 128
#define BN 128
#define BK 64
#define MAXSLOT (TN*NK + NE*BM)   // 9216
#define MAXMT   (MAXSLOT/BM)      // 72
#define STAGE1 49152              // GEMM1: A 16K | Bg 16K | Bu 16K
#define STAGE2 32768              // GEMM2: A 16K | B 16K
#define G1_SMEM (4*STAGE1)        // 192 KB
#define G2_SMEM (3*STAGE2)        // 96 KB  (2 CTAs/SM)

// ---------------- device scratch ----------------
static __device__ __align__(16) __half g_x1 [(size_t)MAXSLOT*HD];    // x fp16
static __device__ __align__(16) __half g_wg [(size_t)NE*ID*HD];      // gate W^T fp16
static __device__ __align__(16) __half g_wu [(size_t)NE*ID*HD];      // up   W^T fp16
static __device__ __align__(16) __half g_wd [(size_t)NE*HD*ID];      // down W^T fp16
static __device__ __align__(16) __half g_a1 [(size_t)MAXSLOT*ID];    // act fp16
static __device__ __align__(16) float g_y  [(size_t)MAXSLOT*HD];
static __device__ int   g_cnt[NE];
static __device__ int   g_cnt2[NE];
static __device__ int   g_off[NE];
static __device__ int   g_tok_e[TN*NK];
static __device__ float g_tok_w[TN*NK];
static __device__ int   g_tok_slot[TN*NK];
static __device__ int   g_slot_token[MAXSLOT];
static __device__ int   g_tile_e[MAXMT];

// ---------------- helpers ----------------
__device__ __forceinline__ uint32_t smem_u32(const void* p) {
    uint32_t a;
    asm("{ .reg .u64 t; cvta.to.shared.u64 t, %1; cvt.u32.u64 %0, t; }" : "=r"(a) : "l"(p));
    return a;
}
__device__ __forceinline__ void cp16(uint32_t dst, const void* src) {
    asm volatile("cp.async.cg.shared.global [%0], [%1], 16;" :: "r"(dst), "l"(src));
}
#define CP_COMMIT() asm volatile("cp.async.commit_group;" ::: "memory")
#define CP_WAIT1()  asm volatile("cp.async.wait_group 1;" ::: "memory")
#define CP_WAIT2()  asm volatile("cp.async.wait_group 2;" ::: "memory")
__device__ __forceinline__ void ldsm4(uint32_t* r, uint32_t addr) {
    asm volatile("ldmatrix.sync.aligned.m8n8.x4.shared.b16 {%0,%1,%2,%3}, [%4];"
        : "=r"(r[0]), "=r"(r[1]), "=r"(r[2]), "=r"(r[3]) : "r"(addr));
}
__device__ __forceinline__ void mmah(float* d, const uint32_t* a, uint32_t b0, uint32_t b1) {
    asm volatile("mma.sync.aligned.m16n8k16.row.col.f32.f16.f16.f32 "
        "{%0,%1,%2,%3}, {%4,%5,%6,%7}, {%8,%9}, {%0,%1,%2,%3};"
        : "+f"(d[0]), "+f"(d[1]), "+f"(d[2]), "+f"(d[3])
        : "r"(a[0]), "r"(a[1]), "r"(a[2]), "r"(a[3]), "r"(b0), "r"(b1));
}
__device__ __forceinline__ float gelu_tanh(float v) {
    float v3 = v * v * v;
    return 0.5f * v * (1.0f + tanhf(0.7978845608028654f * (v + 0.044715f * v3)));
}
__device__ __forceinline__ uint32_t packh2(float a, float b) {
    __half ha = __float2half_rn(a), hb = __float2half_rn(b);
    return (uint32_t)__half_as_ushort(ha) | ((uint32_t)__half_as_ushort(hb) << 16);
}

// ---------------- routing ----------------
__global__ void k_zero() {
    if (threadIdx.x < NE) { g_cnt[threadIdx.x] = 0; g_cnt2[threadIdx.x] = 0; }
}

__global__ void k_router(const float* __restrict__ x, const float* __restrict__ gw,
                         float* __restrict__ out_logits) {
    const int t = blockIdx.x;
    const int tid = threadIdx.x;
    float acc[NE];
#pragma unroll
    for (int e = 0; e < NE; e++) acc[e] = 0.f;
    const float* xr = x + (size_t)t * HD;
    for (int h = tid; h < HD; h += 256) {
        float xv = xr[h];
        const float* g = gw + (size_t)h * NE;
#pragma unroll
        for (int e = 0; e < NE; e++) acc[e] += xv * g[e];
    }
    __shared__ float red[256][NE];
#pragma unroll
    for (int e = 0; e < NE; e++) red[tid][e] = acc[e];
    __syncthreads();
    for (int off = 128; off > 0; off >>= 1) {
        if (tid < off) {
#pragma unroll
            for (int e = 0; e < NE; e++) red[tid][e] += red[tid + off][e];
        }
        __syncthreads();
    }
    if (tid == 0) {
        float l[NE];
#pragma unroll
        for (int e = 0; e < NE; e++) l[e] = red[0][e];
        if (out_logits) {
#pragma unroll
            for (int e = 0; e < NE; e++) out_logits[(size_t)t * NE + e] = l[e];
        }
        int e0 = 0;
#pragma unroll
        for (int e = 1; e < NE; e++) if (l[e] > l[e0]) e0 = e;
        int e1 = -1; float l1 = -1e30f;
#pragma unroll
        for (int e = 0; e < NE; e++) if (e != e0 && l[e] > l1) { l1 = l[e]; e1 = e; }
        float d = expf(l1 - l[e0]);
        float w0 = 1.f / (1.f + d);
        g_tok_e[2*t] = e0; g_tok_e[2*t+1] = e1;
        g_tok_w[2*t] = w0; g_tok_w[2*t+1] = 1.f - w0;
        atomicAdd(&g_cnt[e0], 1);
        atomicAdd(&g_cnt[e1], 1);
    }
}

__global__ void k_offsets() {
    const int tid = threadIdx.x;
    if (tid == 0) {
        int cur = 0, mt = 0;
        for (int e = 0; e < NE; e++) {
            g_off[e] = cur;
            int tiles = (g_cnt[e] + BM - 1) / BM;
            for (int j = 0; j < tiles; j++) g_tile_e[mt++] = e;
            cur += tiles * BM;
        }
        for (; mt < MAXMT; mt++) g_tile_e[mt] = -1;
    }
    for (int i = tid; i < MAXSLOT; i += blockDim.x) g_slot_token[i] = -1;
}

__global__ void k_scatter() {
    int t = blockIdx.x * blockDim.x + threadIdx.x;
    if (t >= TN) return;
#pragma unroll
    for (int k = 0; k < NK; k++) {
        int e = g_tok_e[2*t + k];
        int pos = atomicAdd(&g_cnt2[e], 1);
        int slot = g_off[e] + pos;
        g_slot_token[slot] = t;
        g_tok_slot[2*t + k] = slot;
    }
}

// ---------------- prep: weight transpose + fp16 convert -> [E][N][K] ----------------
__global__ void k_prepw(const float* __restrict__ src, __half* __restrict__ dst,
                        int K, int N) {
    __shared__ float s[32][129];
    int e = blockIdx.z;
    int n0 = blockIdx.x * 128, k0 = blockIdx.y * 32;
    const float* sp = src + (size_t)e * K * N;
    for (int idx = threadIdx.x; idx < 32 * 128; idx += 256) {
        int r = idx >> 7, c = idx & 127;
        s[r][c] = sp[(size_t)(k0 + r) * N + n0 + c];
    }
    __syncthreads();
    __half* dp = dst + (size_t)e * N * K;
    for (int idx = threadIdx.x; idx < 2048; idx += 256) {
        int n = idx >> 4, kp = (idx & 15) << 1;
        *(uint32_t*)&dp[(size_t)(n0 + n) * K + k0 + kp] = packh2(s[kp][n], s[kp + 1][n]);
    }
}

// ---------------- prep: gather x rows per slot -> fp16 ----------------
__global__ void k_gatherx(const float* __restrict__ x) {
    int slot = blockIdx.x;
    int t = g_slot_token[slot];
    __half* row = g_x1 + (size_t)slot * HD;
    for (int k = threadIdx.x * 2; k < HD; k += 512) {
        float v0 = 0.f, v1 = 0.f;
        if (t >= 0) {
            v0 = x[(size_t)t * HD + k];
            v1 = x[(size_t)t * HD + k + 1];
        }
        *(uint32_t*)&row[k] = packh2(v0, v1);
    }
}

// ---------------- GEMM1 fused: g = x@Wg, u = x@Wu, act = gelu(g)*u -> fp16 ----------------
// grid (MAXMT, ID/128), 256 thr, 4-stage. Stage 48K: A 16K | Bg 16K | Bu 16K
__global__ void __launch_bounds__(256, 1)
k_gemm1f(const __half* __restrict__ A, const __half* __restrict__ Bg,
         const __half* __restrict__ Bu) {
    const int mt = blockIdx.x;
    const int e = g_tile_e[mt];
    if (e < 0) return;
    const int m0 = mt * BM;
    const int n0 = blockIdx.y * BN;
    extern __shared__ char smraw[];
    const uint32_t sbase = smem_u32(smraw);
    const int tid = threadIdx.x, lane = tid & 31, wid = tid >> 5;
    const int wm = (wid >> 2) * 64, wn = (wid & 3) * 32;
    const int Kc = HD / BK;   // 32

    const int prow = tid >> 3, pkc = tid & 7;
    const uint32_t sw = ((uint32_t)(pkc ^ (prow & 7))) << 4;
    const __half* aptr = A + (size_t)(m0 + prow) * HD + pkc * 8;
    const __half* bgp = Bg + ((size_t)e * ID + n0 + prow) * HD + pkc * 8;
    const __half* bup = Bu + ((size_t)e * ID + n0 + prow) * HD + pkc * 8;

    auto load_stage = [&](int s, int c) {
        uint32_t d = sbase + s * STAGE1;
        const __half* a = aptr + c * BK;
        const __half* bg = bgp + c * BK;
        const __half* bu = bup + c * BK;
#pragma unroll
        for (int t = 0; t < 4; t++) {
            uint32_t dd = d + (prow + 32*t) * 128 + sw;
            cp16(dd,          a  + (size_t)(32*t) * HD);
            cp16(dd + 16384,  bg + (size_t)(32*t) * HD);
            cp16(dd + 32768,  bu + (size_t)(32*t) * HD);
        }
    };

    load_stage(0, 0); CP_COMMIT();
    load_stage(1, 1); CP_COMMIT();
    load_stage(2, 2); CP_COMMIT();

    float accg[4][4][4], accu[4][4][4];
#pragma unroll
    for (int i = 0; i < 4; i++)
#pragma unroll
        for (int j = 0; j < 4; j++)
#pragma unroll
            for (int q = 0; q < 4; q++) { accg[i][j][q] = 0.f; accu[i][j][q] = 0.f; }

    const int lrow = lane & 15, lk = lane >> 4;

    for (int c = 0; c < Kc; c++) {
        CP_WAIT2();
        __syncthreads();
        if (c + 3 < Kc) load_stage((c + 3) & 3, c + 3);
        CP_COMMIT();
        const uint32_t sa = sbase + (c & 3) * STAGE1;
#pragma unroll
        for (int ks = 0; ks < 4; ks++) {
            uint32_t ah[4][4], bgf[2][4], buf[2][4];
            const int kc = ks * 2 + lk;
#pragma unroll
            for (int mi = 0; mi < 4; mi++) {
                int row = wm + mi * 16 + lrow;
                ldsm4(ah[mi], sa + row * 128 + ((kc ^ (row & 7)) << 4));
            }
#pragma unroll
            for (int ng = 0; ng < 2; ng++) {
                int row = wn + ng * 16 + lrow;
                uint32_t bd = sa + 16384 + row * 128 + ((kc ^ (row & 7)) << 4);
                ldsm4(bgf[ng], bd);
                ldsm4(buf[ng], bd + 16384);
            }
#pragma unroll
            for (int mi = 0; mi < 4; mi++)
#pragma unroll
                for (int nf = 0; nf < 4; nf++) {
                    const int ng = nf >> 1, p = nf & 1;
                    mmah(accg[mi][nf], ah[mi], bgf[ng][p], bgf[ng][p + 2]);
                    mmah(accu[mi][nf], ah[mi], buf[ng][p], buf[ng][p + 2]);
                }
        }
    }

    // epilogue: gelu(g)*u in registers -> fp16 act
    const int r0 = lane >> 2, c0 = (lane & 3) * 2;
#pragma unroll
    for (int mi = 0; mi < 4; mi++)
#pragma unroll
        for (int nf = 0; nf < 4; nf++) {
            int grow = m0 + wm + mi * 16 + r0;
            int col = n0 + wn + nf * 8 + c0;
            float a0 = gelu_tanh(accg[mi][nf][0]) * accu[mi][nf][0];
            float a1 = gelu_tanh(accg[mi][nf][1]) * accu[mi][nf][1];
            float a2 = gelu_tanh(accg[mi][nf][2]) * accu[mi][nf][2];
            float a3 = gelu_tanh(accg[mi][nf][3]) * accu[mi][nf][3];
            *(uint32_t*)(g_a1 + (size_t)grow * ID + col) = packh2(a0, a1);
            *(uint32_t*)(g_a1 + (size_t)(grow + 8) * ID + col) = packh2(a2, a3);
        }
}

// ---------------- GEMM2: y = act @ Wd (plain fp16, 3-stage, 2 CTAs/SM) ----------------
__global__ void __launch_bounds__(256, 2)
k_gemm2(const __half* __restrict__ A, const __half* __restrict__ B,
        float* __restrict__ C) {
    const int mt = blockIdx.x;
    const int e = g_tile_e[mt];
    if (e < 0) return;
    const int m0 = mt * BM;
    const int n0 = blockIdx.y * BN;
    extern __shared__ char smraw[];
    const uint32_t sbase = smem_u32(smraw);
    const int tid = threadIdx.x, lane = tid & 31, wid = tid >> 5;
    const int wm = (wid >> 2) * 64, wn = (wid & 3) * 32;
    const int Kc = ID / BK;   // 64

    const int prow = tid >> 3, pkc = tid & 7;
    const uint32_t sw = ((uint32_t)(pkc ^ (prow & 7))) << 4;
    const __half* aptr = A + (size_t)(m0 + prow) * ID + pkc * 8;
    const __half* bptr = B + ((size_t)e * HD + n0 + prow) * ID + pkc * 8;

    auto load_stage = [&](int s, int c) {
        uint32_t d = sbase + s * STAGE2;
        const __half* a = aptr + c * BK;
        const __half* b = bptr + c * BK;
#pragma unroll
        for (int t = 0; t < 4; t++) {
            uint32_t dd = d + (prow + 32*t) * 128 + sw;
            cp16(dd,          a + (size_t)(32*t) * ID);
            cp16(dd + 16384,  b + (size_t)(32*t) * ID);
        }
    };

    load_stage(0, 0); CP_COMMIT();
    load_stage(1, 1); CP_COMMIT();

    float acc[4][4][4];
#pragma unroll
    for (int i = 0; i < 4; i++)
#pragma unroll
        for (int j = 0; j < 4; j++)
#pragma unroll
            for (int q = 0; q < 4; q++) acc[i][j][q] = 0.f;

    const int lrow = lane & 15, lk = lane >> 4;

    for (int c = 0; c < Kc; c++) {
        CP_WAIT1();
        __syncthreads();
        if (c + 2 < Kc) load_stage((c + 2) % 3, c + 2);
        CP_COMMIT();
        const uint32_t sa = sbase + (c % 3) * STAGE2;
#pragma unroll
        for (int ks = 0; ks < 4; ks++) {
            uint32_t ah[4][4], bf[2][4];
            const int kc = ks * 2 + lk;
#pragma unroll
            for (int mi = 0; mi < 4; mi++) {
                int row = wm + mi * 16 + lrow;
                ldsm4(ah[mi], sa + row * 128 + ((kc ^ (row & 7)) << 4));
            }
#pragma unroll
            for (int ng = 0; ng < 2; ng++) {
                int row = wn + ng * 16 + lrow;
                ldsm4(bf[ng], sa + 16384 + row * 128 + ((kc ^ (row & 7)) << 4));
            }
#pragma unroll
            for (int mi = 0; mi < 4; mi++)
#pragma unroll
                for (int nf = 0; nf < 4; nf++) {
                    const int ng = nf >> 1, p = nf & 1;
                    mmah(acc[mi][nf], ah[mi], bf[ng][p], bf[ng][p + 2]);
                }
        }
    }

#pragma unroll
    for (int mi = 0; mi < 4; mi++)
#pragma unroll
        for (int nf = 0; nf < 4; nf++) {
            int row = m0 + wm + mi * 16 + (lane >> 2);
            int col = n0 + wn + nf * 8 + (lane & 3) * 2;
            float2* p0 = (float2*)&C[(size_t)row * HD + col];
            p0->x = acc[mi][nf][0]; p0->y = acc[mi][nf][1];
            float2* p1 = (float2*)&C[(size_t)(row + 8) * HD + col];
            p1->x = acc[mi][nf][2]; p1->y = acc[mi][nf][3];
        }
}

// ---------------- combine ----------------
__global__ void k_combine(float* __restrict__ out) {
    int idx = blockIdx.x * blockDim.x + threadIdx.x;
    int t = idx / (HD / 4);
    int c = (idx % (HD / 4)) * 4;
    int s0 = g_tok_slot[2*t], s1 = g_tok_slot[2*t+1];
    float w0 = g_tok_w[2*t], w1 = g_tok_w[2*t+1];
    float4 y0 = *(const float4*)&g_y[(size_t)s0 * HD + c];
    float4 y1 = *(const float4*)&g_y[(size_t)s1 * HD + c];
    float4 r;
    r.x = w0*y0.x + w1*y1.x; r.y = w0*y0.y + w1*y1.y;
    r.z = w0*y0.z + w1*y1.z; r.w = w0*y0.w + w1*y1.w;
    *(float4*)&out[(size_t)t * HD + c] = r;
}

// ---------------- host ----------------
extern "C" void kernel_launch(void* const* d_in, const int* in_sizes, int n_in,
                              void* d_out, int out_size) {
    const float* x  = (const float*)d_in[0];
    const float* gw = (const float*)d_in[1];
    const float* wg = (const float*)d_in[2];
    const float* wu = (const float*)d_in[3];
    const float* wd = (const float*)d_in[4];
    float* out = (float*)d_out;

    float* logits = nullptr;
    if ((long long)out_size >= (long long)TN * HD + (long long)TN * NE)
        logits = out + (size_t)TN * HD;

    void *p_wg, *p_wu, *p_wd, *p_x1, *p_a1, *p_y;
    cudaGetSymbolAddress(&p_wg, g_wg);
    cudaGetSymbolAddress(&p_wu, g_wu);
    cudaGetSymbolAddress(&p_wd, g_wd);
    cudaGetSymbolAddress(&p_x1, g_x1);
    cudaGetSymbolAddress(&p_a1, g_a1);
    cudaGetSymbolAddress(&p_y, g_y);

    cudaFuncSetAttribute(k_gemm1f, cudaFuncAttributeMaxDynamicSharedMemorySize, G1_SMEM);
    cudaFuncSetAttribute(k_gemm2,  cudaFuncAttributeMaxDynamicSharedMemorySize, G2_SMEM);

    k_zero<<<1, 32>>>();
    k_router<<<TN, 256>>>(x, gw, logits);
    k_offsets<<<1, 256>>>();
    k_scatter<<<TN / 256, 256>>>();
    k_gatherx<<<MAXSLOT, 256>>>(x);
    k_prepw<<<dim3(ID/128, HD/32, NE), 256>>>(wg, (__half*)p_wg, HD, ID);
    k_prepw<<<dim3(ID/128, HD/32, NE), 256>>>(wu, (__half*)p_wu, HD, ID);
    k_prepw<<<dim3(HD/128, ID/32, NE), 256>>>(wd, (__half*)p_wd, ID, HD);
    k_gemm1f<<<dim3(MAXMT, ID/BN), 256, G1_SMEM>>>(
        (const __half*)p_x1, (const __half*)p_wg, (const __half*)p_wu);
    k_gemm2<<<dim3(MAXMT, HD/BN), 256, G2_SMEM>>>(
        (const __half*)p_a1, (const __half*)p_wd, (float*)p_y);
    k_combine<<<(TN * HD / 4) / 256, 256>>>(out);
}

// round 7
// speedup vs baseline: 6.3738x; 1.1362x over previous
#include <cuda_runtime.h>
#include <cuda_fp16.h>
#include <math.h>
#include <stdint.h>

// ---------------- problem constants ----------------
#define TN 4096
#define HD 2048
#define ID 4096
#define NE 8
#define NK 2
#define BM 128
#define BN 128
#define BK 64
#define MAXSLOT (TN*NK + NE*BM)   // 9216
#define MAXMT   (MAXSLOT/BM)      // 72
#define STAGE 32768               // A 16K | B 16K
#define G_SMEM (3*STAGE)          // 96 KB -> 2 CTAs/SM

// ---------------- device scratch ----------------
static __device__ __align__(16) __half g_x1 [(size_t)MAXSLOT*HD];      // x fp16
static __device__ __align__(16) __half g_w1 [(size_t)NE*2*ID*HD];      // interleaved gate/up B' fp16
static __device__ __align__(16) __half g_wd [(size_t)NE*HD*ID];        // down W^T fp16
static __device__ __align__(16) __half g_a1 [(size_t)MAXSLOT*ID];      // act fp16
static __device__ __align__(16) float g_y  [(size_t)MAXSLOT*HD];
static __device__ int   g_cnt[NE];
static __device__ int   g_cnt2[NE];
static __device__ int   g_off[NE];
static __device__ int   g_tok_e[TN*NK];
static __device__ float g_tok_w[TN*NK];
static __device__ int   g_tok_slot[TN*NK];
static __device__ int   g_slot_token[MAXSLOT];
static __device__ int   g_tile_e[MAXMT];

// ---------------- helpers ----------------
__device__ __forceinline__ uint32_t smem_u32(const void* p) {
    uint32_t a;
    asm("{ .reg .u64 t; cvta.to.shared.u64 t, %1; cvt.u32.u64 %0, t; }" : "=r"(a) : "l"(p));
    return a;
}
__device__ __forceinline__ void cp16(uint32_t dst, const void* src) {
    asm volatile("cp.async.cg.shared.global [%0], [%1], 16;" :: "r"(dst), "l"(src));
}
#define CP_COMMIT() asm volatile("cp.async.commit_group;" ::: "memory")
#define CP_WAIT1()  asm volatile("cp.async.wait_group 1;" ::: "memory")
__device__ __forceinline__ void ldsm4(uint32_t* r, uint32_t addr) {
    asm volatile("ldmatrix.sync.aligned.m8n8.x4.shared.b16 {%0,%1,%2,%3}, [%4];"
        : "=r"(r[0]), "=r"(r[1]), "=r"(r[2]), "=r"(r[3]) : "r"(addr));
}
__device__ __forceinline__ void mmah(float* d, const uint32_t* a, uint32_t b0, uint32_t b1) {
    asm volatile("mma.sync.aligned.m16n8k16.row.col.f32.f16.f16.f32 "
        "{%0,%1,%2,%3}, {%4,%5,%6,%7}, {%8,%9}, {%0,%1,%2,%3};"
        : "+f"(d[0]), "+f"(d[1]), "+f"(d[2]), "+f"(d[3])
        : "r"(a[0]), "r"(a[1]), "r"(a[2]), "r"(a[3]), "r"(b0), "r"(b1));
}
__device__ __forceinline__ float gelu_tanh(float v) {
    float v3 = v * v * v;
    return 0.5f * v * (1.0f + tanhf(0.7978845608028654f * (v + 0.044715f * v3)));
}
__device__ __forceinline__ uint32_t packh2(float a, float b) {
    __half ha = __float2half_rn(a), hb = __float2half_rn(b);
    return (uint32_t)__half_as_ushort(ha) | ((uint32_t)__half_as_ushort(hb) << 16);
}

// ---------------- routing ----------------
__global__ void k_zero() {
    if (threadIdx.x < NE) { g_cnt[threadIdx.x] = 0; g_cnt2[threadIdx.x] = 0; }
}

__global__ void k_router(const float* __restrict__ x, const float* __restrict__ gw,
                         float* __restrict__ out_logits) {
    const int t = blockIdx.x;
    const int tid = threadIdx.x;
    float acc[NE];
#pragma unroll
    for (int e = 0; e < NE; e++) acc[e] = 0.f;
    const float* xr = x + (size_t)t * HD;
    for (int h = tid; h < HD; h += 256) {
        float xv = xr[h];
        const float* g = gw + (size_t)h * NE;
#pragma unroll
        for (int e = 0; e < NE; e++) acc[e] += xv * g[e];
    }
    __shared__ float red[256][NE];
#pragma unroll
    for (int e = 0; e < NE; e++) red[tid][e] = acc[e];
    __syncthreads();
    for (int off = 128; off > 0; off >>= 1) {
        if (tid < off) {
#pragma unroll
            for (int e = 0; e < NE; e++) red[tid][e] += red[tid + off][e];
        }
        __syncthreads();
    }
    if (tid == 0) {
        float l[NE];
#pragma unroll
        for (int e = 0; e < NE; e++) l[e] = red[0][e];
        if (out_logits) {
#pragma unroll
            for (int e = 0; e < NE; e++) out_logits[(size_t)t * NE + e] = l[e];
        }
        int e0 = 0;
#pragma unroll
        for (int e = 1; e < NE; e++) if (l[e] > l[e0]) e0 = e;
        int e1 = -1; float l1 = -1e30f;
#pragma unroll
        for (int e = 0; e < NE; e++) if (e != e0 && l[e] > l1) { l1 = l[e]; e1 = e; }
        float d = expf(l1 - l[e0]);
        float w0 = 1.f / (1.f + d);
        g_tok_e[2*t] = e0; g_tok_e[2*t+1] = e1;
        g_tok_w[2*t] = w0; g_tok_w[2*t+1] = 1.f - w0;
        atomicAdd(&g_cnt[e0], 1);
        atomicAdd(&g_cnt[e1], 1);
    }
}

__global__ void k_offsets() {
    const int tid = threadIdx.x;
    if (tid == 0) {
        int cur = 0, mt = 0;
        for (int e = 0; e < NE; e++) {
            g_off[e] = cur;
            int tiles = (g_cnt[e] + BM - 1) / BM;
            for (int j = 0; j < tiles; j++) g_tile_e[mt++] = e;
            cur += tiles * BM;
        }
        for (; mt < MAXMT; mt++) g_tile_e[mt] = -1;
    }
    for (int i = tid; i < MAXSLOT; i += blockDim.x) g_slot_token[i] = -1;
}

__global__ void k_scatter() {
    int t = blockIdx.x * blockDim.x + threadIdx.x;
    if (t >= TN) return;
#pragma unroll
    for (int k = 0; k < NK; k++) {
        int e = g_tok_e[2*t + k];
        int pos = atomicAdd(&g_cnt2[e], 1);
        int slot = g_off[e] + pos;
        g_slot_token[slot] = t;
        g_tok_slot[2*t + k] = slot;
    }
}

// ---------------- prep: weight transpose + fp16 convert, 128B-coalesced writes ----------------
// src: [E][K][N] fp32  ->  dst rows (n-major) with stride K, fp16.
// mode 0: row = n (direct, for Wd)
// mode 1: row = (n>>6)*128 + (n&63)        (gate cols -> first 64 of each 128-row block)
// mode 2: row = (n>>6)*128 + (n&63) + 64   (up cols   -> second 64)
__global__ void k_prepw(const float* __restrict__ src, __half* __restrict__ dst,
                        int K, int N, int nrows, int mode) {
    __shared__ float s[64 * 129];
    const int e = blockIdx.z;
    const int n0 = blockIdx.x * 128, k0 = blockIdx.y * 64;
    const float* sp = src + (size_t)e * K * N + (size_t)k0 * N + n0;
#pragma unroll
    for (int i = 0; i < 8; i++) {
        int q = threadIdx.x + i * 256;           // 0..2047 float4 pieces
        int kr = q >> 5, c4 = (q & 31) * 4;
        float4 v = *(const float4*)(sp + (size_t)kr * N + c4);
        float* d = s + kr * 129 + c4;
        d[0] = v.x; d[1] = v.y; d[2] = v.z; d[3] = v.w;
    }
    __syncthreads();
    __half* dp = dst + (size_t)e * nrows * K + k0;
#pragma unroll
    for (int i = 0; i < 4; i++) {
        int j = threadIdx.x + i * 256;           // 0..1023 uint4 pieces
        int n = j >> 3, kq = (j & 7) * 8;
        uint32_t w[4];
#pragma unroll
        for (int t = 0; t < 4; t++)
            w[t] = packh2(s[(kq + 2*t) * 129 + n], s[(kq + 2*t + 1) * 129 + n]);
        int ng = n0 + n;
        size_t row;
        if (mode == 0)      row = (size_t)ng;
        else if (mode == 1) row = (size_t)(ng >> 6) * 128 + (ng & 63);
        else                row = (size_t)(ng >> 6) * 128 + (ng & 63) + 64;
        *(uint4*)(dp + row * K + kq) = *(uint4*)w;
    }
}

// ---------------- prep: gather x rows per slot -> fp16 ----------------
__global__ void k_gatherx(const float* __restrict__ x) {
    int slot = blockIdx.x;
    int t = g_slot_token[slot];
    __half* row = g_x1 + (size_t)slot * HD;
    for (int k = threadIdx.x * 2; k < HD; k += 512) {
        float v0 = 0.f, v1 = 0.f;
        if (t >= 0) {
            v0 = x[(size_t)t * HD + k];
            v1 = x[(size_t)t * HD + k + 1];
        }
        *(uint32_t*)&row[k] = packh2(v0, v1);
    }
}

// ---------------- GEMM1: C' = x @ B' (interleaved gate|up), fused gelu epilogue ----------------
// grid (MAXMT, 2*ID/128=64), 256 thr, 3-stage 32KB, 2 CTAs/SM.
__global__ void __launch_bounds__(256, 2)
k_gemm1i(const __half* __restrict__ A, const __half* __restrict__ B) {
    const int mt = blockIdx.x;
    const int e = g_tile_e[mt];
    if (e < 0) return;
    const int m0 = mt * BM;
    const int nb0 = blockIdx.y * 128;            // B' row offset
    extern __shared__ char smraw[];
    const uint32_t sbase = smem_u32(smraw);
    const int tid = threadIdx.x, lane = tid & 31, wid = tid >> 5;
    const int wm = (wid >> 2) * 64, wn = (wid & 3) * 32;
    const int Kc = HD / BK;   // 32

    const int prow = tid >> 3, pkc = tid & 7;
    const uint32_t sw = ((uint32_t)(pkc ^ (prow & 7))) << 4;
    const __half* aptr = A + (size_t)(m0 + prow) * HD + pkc * 8;
    const __half* bptr = B + ((size_t)e * (2 * ID) + nb0 + prow) * HD + pkc * 8;

    auto load_stage = [&](int s, int c) {
        uint32_t d = sbase + s * STAGE;
        const __half* a = aptr + c * BK;
        const __half* b = bptr + c * BK;
#pragma unroll
        for (int t = 0; t < 4; t++) {
            uint32_t dd = d + (prow + 32*t) * 128 + sw;
            cp16(dd,          a + (size_t)(32*t) * HD);
            cp16(dd + 16384,  b + (size_t)(32*t) * HD);
        }
    };

    load_stage(0, 0); CP_COMMIT();
    load_stage(1, 1); CP_COMMIT();

    float acc[4][4][4];
#pragma unroll
    for (int i = 0; i < 4; i++)
#pragma unroll
        for (int j = 0; j < 4; j++)
#pragma unroll
            for (int q = 0; q < 4; q++) acc[i][j][q] = 0.f;

    const int lrow = lane & 15, lk = lane >> 4;

    for (int c = 0; c < Kc; c++) {
        CP_WAIT1();
        __syncthreads();
        if (c + 2 < Kc) load_stage((c + 2) % 3, c + 2);
        CP_COMMIT();
        const uint32_t sa = sbase + (c % 3) * STAGE;
#pragma unroll
        for (int ks = 0; ks < 4; ks++) {
            uint32_t ah[4][4], bf[2][4];
            const int kc = ks * 2 + lk;
#pragma unroll
            for (int mi = 0; mi < 4; mi++) {
                int row = wm + mi * 16 + lrow;
                ldsm4(ah[mi], sa + row * 128 + ((kc ^ (row & 7)) << 4));
            }
#pragma unroll
            for (int ng = 0; ng < 2; ng++) {
                int row = wn + ng * 16 + lrow;
                ldsm4(bf[ng], sa + 16384 + row * 128 + ((kc ^ (row & 7)) << 4));
            }
#pragma unroll
            for (int mi = 0; mi < 4; mi++)
#pragma unroll
                for (int nf = 0; nf < 4; nf++) {
                    const int ng = nf >> 1, p = nf & 1;
                    mmah(acc[mi][nf], ah[mi], bf[ng][p], bf[ng][p + 2]);
                }
        }
    }

    // epilogue: tile -> smem fp32 (pitch 132), pair gate col c with up col c+64, gelu, fp16 store
    __syncthreads();
    float* smf = (float*)smraw;
    const int r0 = lane >> 2, c0 = (lane & 3) * 2;
#pragma unroll
    for (int mi = 0; mi < 4; mi++)
#pragma unroll
        for (int nf = 0; nf < 4; nf++) {
            int row = wm + mi * 16 + r0;
            int col = wn + nf * 8 + c0;
            smf[row * 132 + col]           = acc[mi][nf][0];
            smf[row * 132 + col + 1]       = acc[mi][nf][1];
            smf[(row + 8) * 132 + col]     = acc[mi][nf][2];
            smf[(row + 8) * 132 + col + 1] = acc[mi][nf][3];
        }
    __syncthreads();

    const int colbase = blockIdx.y * 64;
#pragma unroll
    for (int i = 0; i < 16; i++) {
        int lin = tid + i * 256;          // 0..4095 = 128 rows x 32 col-pairs
        int row = lin >> 5;
        int cp = (lin & 31) << 1;         // 0..62
        float g0 = smf[row * 132 + cp],      g1 = smf[row * 132 + cp + 1];
        float u0 = smf[row * 132 + cp + 64], u1 = smf[row * 132 + cp + 65];
        float a0 = gelu_tanh(g0) * u0;
        float a1 = gelu_tanh(g1) * u1;
        *(uint32_t*)(g_a1 + (size_t)(m0 + row) * ID + colbase + cp) = packh2(a0, a1);
    }
}

// ---------------- GEMM2: y = act @ Wd (plain fp16, 3-stage, 2 CTAs/SM) ----------------
__global__ void __launch_bounds__(256, 2)
k_gemm2(const __half* __restrict__ A, const __half* __restrict__ B,
        float* __restrict__ C) {
    const int mt = blockIdx.x;
    const int e = g_tile_e[mt];
    if (e < 0) return;
    const int m0 = mt * BM;
    const int n0 = blockIdx.y * BN;
    extern __shared__ char smraw[];
    const uint32_t sbase = smem_u32(smraw);
    const int tid = threadIdx.x, lane = tid & 31, wid = tid >> 5;
    const int wm = (wid >> 2) * 64, wn = (wid & 3) * 32;
    const int Kc = ID / BK;   // 64

    const int prow = tid >> 3, pkc = tid & 7;
    const uint32_t sw = ((uint32_t)(pkc ^ (prow & 7))) << 4;
    const __half* aptr = A + (size_t)(m0 + prow) * ID + pkc * 8;
    const __half* bptr = B + ((size_t)e * HD + n0 + prow) * ID + pkc * 8;

    auto load_stage = [&](int s, int c) {
        uint32_t d = sbase + s * STAGE;
        const __half* a = aptr + c * BK;
        const __half* b = bptr + c * BK;
#pragma unroll
        for (int t = 0; t < 4; t++) {
            uint32_t dd = d + (prow + 32*t) * 128 + sw;
            cp16(dd,          a + (size_t)(32*t) * ID);
            cp16(dd + 16384,  b + (size_t)(32*t) * ID);
        }
    };

    load_stage(0, 0); CP_COMMIT();
    load_stage(1, 1); CP_COMMIT();

    float acc[4][4][4];
#pragma unroll
    for (int i = 0; i < 4; i++)
#pragma unroll
        for (int j = 0; j < 4; j++)
#pragma unroll
            for (int q = 0; q < 4; q++) acc[i][j][q] = 0.f;

    const int lrow = lane & 15, lk = lane >> 4;

    for (int c = 0; c < Kc; c++) {
        CP_WAIT1();
        __syncthreads();
        if (c + 2 < Kc) load_stage((c + 2) % 3, c + 2);
        CP_COMMIT();
        const uint32_t sa = sbase + (c % 3) * STAGE;
#pragma unroll
        for (int ks = 0; ks < 4; ks++) {
            uint32_t ah[4][4], bf[2][4];
            const int kc = ks * 2 + lk;
#pragma unroll
            for (int mi = 0; mi < 4; mi++) {
                int row = wm + mi * 16 + lrow;
                ldsm4(ah[mi], sa + row * 128 + ((kc ^ (row & 7)) << 4));
            }
#pragma unroll
            for (int ng = 0; ng < 2; ng++) {
                int row = wn + ng * 16 + lrow;
                ldsm4(bf[ng], sa + 16384 + row * 128 + ((kc ^ (row & 7)) << 4));
            }
#pragma unroll
            for (int mi = 0; mi < 4; mi++)
#pragma unroll
                for (int nf = 0; nf < 4; nf++) {
                    const int ng = nf >> 1, p = nf & 1;
                    mmah(acc[mi][nf], ah[mi], bf[ng][p], bf[ng][p + 2]);
                }
        }
    }

#pragma unroll
    for (int mi = 0; mi < 4; mi++)
#pragma unroll
        for (int nf = 0; nf < 4; nf++) {
            int row = m0 + wm + mi * 16 + (lane >> 2);
            int col = n0 + wn + nf * 8 + (lane & 3) * 2;
            float2* p0 = (float2*)&C[(size_t)row * HD + col];
            p0->x = acc[mi][nf][0]; p0->y = acc[mi][nf][1];
            float2* p1 = (float2*)&C[(size_t)(row + 8) * HD + col];
            p1->x = acc[mi][nf][2]; p1->y = acc[mi][nf][3];
        }
}

// ---------------- combine ----------------
__global__ void k_combine(float* __restrict__ out) {
    int idx = blockIdx.x * blockDim.x + threadIdx.x;
    int t = idx / (HD / 4);
    int c = (idx % (HD / 4)) * 4;
    int s0 = g_tok_slot[2*t], s1 = g_tok_slot[2*t+1];
    float w0 = g_tok_w[2*t], w1 = g_tok_w[2*t+1];
    float4 y0 = *(const float4*)&g_y[(size_t)s0 * HD + c];
    float4 y1 = *(const float4*)&g_y[(size_t)s1 * HD + c];
    float4 r;
    r.x = w0*y0.x + w1*y1.x; r.y = w0*y0.y + w1*y1.y;
    r.z = w0*y0.z + w1*y1.z; r.w = w0*y0.w + w1*y1.w;
    *(float4*)&out[(size_t)t * HD + c] = r;
}

// ---------------- host ----------------
extern "C" void kernel_launch(void* const* d_in, const int* in_sizes, int n_in,
                              void* d_out, int out_size) {
    const float* x  = (const float*)d_in[0];
    const float* gw = (const float*)d_in[1];
    const float* wg = (const float*)d_in[2];
    const float* wu = (const float*)d_in[3];
    const float* wd = (const float*)d_in[4];
    float* out = (float*)d_out;

    float* logits = nullptr;
    if ((long long)out_size >= (long long)TN * HD + (long long)TN * NE)
        logits = out + (size_t)TN * HD;

    void *p_w1, *p_wd, *p_x1, *p_a1, *p_y;
    cudaGetSymbolAddress(&p_w1, g_w1);
    cudaGetSymbolAddress(&p_wd, g_wd);
    cudaGetSymbolAddress(&p_x1, g_x1);
    cudaGetSymbolAddress(&p_a1, g_a1);
    cudaGetSymbolAddress(&p_y, g_y);

    cudaFuncSetAttribute(k_gemm1i, cudaFuncAttributeMaxDynamicSharedMemorySize, G_SMEM);
    cudaFuncSetAttribute(k_gemm2,  cudaFuncAttributeMaxDynamicSharedMemorySize, G_SMEM);

    k_zero<<<1, 32>>>();
    k_router<<<TN, 256>>>(x, gw, logits);
    k_offsets<<<1, 256>>>();
    k_scatter<<<TN / 256, 256>>>();
    k_gatherx<<<MAXSLOT, 256>>>(x);
    // gate/up -> interleaved B' (8192 rows/expert); down -> direct (2048 rows/expert)
    k_prepw<<<dim3(ID/128, HD/64, NE), 256>>>(wg, (__half*)p_w1, HD, ID, 2*ID, 1);
    k_prepw<<<dim3(ID/128, HD/64, NE), 256>>>(wu, (__half*)p_w1, HD, ID, 2*ID, 2);
    k_prepw<<<dim3(HD/128, ID/64, NE), 256>>>(wd, (__half*)p_wd, ID, HD, HD, 0);
    k_gemm1i<<<dim3(MAXMT, (2*ID)/128), 256, G_SMEM>>>(
        (const __half*)p_x1, (const __half*)p_w1);
    k_gemm2<<<dim3(MAXMT, HD/BN), 256, G_SMEM>>>(
        (const __half*)p_a1, (const __half*)p_wd, (float*)p_y);
    k_combine<<<(TN * HD / 4) / 256, 256>>>(out);
}

// round 9
// speedup vs baseline: 6.4831x; 1.0171x over previous
#include <cuda_runtime.h>
#include <cuda_fp16.h>
#include <math.h>
#include <stdint.h>

// ---------------- problem constants ----------------
#define TN 4096
#define HD 2048
#define ID 4096
#define NE 8
#define NK 2
#define BM 128
#define BN 128
#define BK 64
#define MAXSLOT (TN*NK + NE*BM)   // 9216
#define MAXMT   (MAXSLOT/BM)      // 72
#define STAGE 32768               // A 16K | B 16K
#define G_SMEM (3*STAGE)          // 96 KB -> 2 CTAs/SM

// ---------------- device scratch ----------------
static __device__ __align__(16) __half g_x1 [(size_t)MAXSLOT*HD];      // x fp16
static __device__ __align__(16) __half g_w1 [(size_t)NE*2*ID*HD];      // fine-interleaved gate/up B' fp16
static __device__ __align__(16) __half g_wd [(size_t)NE*HD*ID];        // down W^T fp16
static __device__ __align__(16) __half g_a1 [(size_t)MAXSLOT*ID];      // act fp16
static __device__ __align__(16) float g_y  [(size_t)MAXSLOT*HD];
static __device__ int   g_cnt[NE];
static __device__ int   g_cnt2[NE];
static __device__ int   g_off[NE];
static __device__ int   g_tok_e[TN*NK];
static __device__ float g_tok_w[TN*NK];
static __device__ int   g_tok_slot[TN*NK];
static __device__ int   g_slot_token[MAXSLOT];
static __device__ int   g_tile_e[MAXMT];

// ---------------- helpers ----------------
__device__ __forceinline__ uint32_t smem_u32(const void* p) {
    uint32_t a;
    asm("{ .reg .u64 t; cvta.to.shared.u64 t, %1; cvt.u32.u64 %0, t; }" : "=r"(a) : "l"(p));
    return a;
}
__device__ __forceinline__ void cp16(uint32_t dst, const void* src) {
    asm volatile("cp.async.cg.shared.global [%0], [%1], 16;" :: "r"(dst), "l"(src));
}
#define CP_COMMIT() asm volatile("cp.async.commit_group;" ::: "memory")
#define CP_WAIT1()  asm volatile("cp.async.wait_group 1;" ::: "memory")
__device__ __forceinline__ void ldsm4(uint32_t* r, uint32_t addr) {
    asm volatile("ldmatrix.sync.aligned.m8n8.x4.shared.b16 {%0,%1,%2,%3}, [%4];"
        : "=r"(r[0]), "=r"(r[1]), "=r"(r[2]), "=r"(r[3]) : "r"(addr));
}
__device__ __forceinline__ void mmah(float* d, const uint32_t* a, uint32_t b0, uint32_t b1) {
    asm volatile("mma.sync.aligned.m16n8k16.row.col.f32.f16.f16.f32 "
        "{%0,%1,%2,%3}, {%4,%5,%6,%7}, {%8,%9}, {%0,%1,%2,%3};"
        : "+f"(d[0]), "+f"(d[1]), "+f"(d[2]), "+f"(d[3])
        : "r"(a[0]), "r"(a[1]), "r"(a[2]), "r"(a[3]), "r"(b0), "r"(b1));
}
__device__ __forceinline__ float gelu_tanh(float v) {
    float w = 0.7978845608028654f * v * (1.0f + 0.044715f * v * v);
    float t;
    asm("tanh.approx.f32 %0, %1;" : "=f"(t) : "f"(w));
    return 0.5f * v * (1.0f + t);
}
__device__ __forceinline__ uint32_t packh2(float a, float b) {
    __half ha = __float2half_rn(a), hb = __float2half_rn(b);
    return (uint32_t)__half_as_ushort(ha) | ((uint32_t)__half_as_ushort(hb) << 16);
}

// ---------------- routing ----------------
__global__ void k_zero() {
    if (threadIdx.x < NE) { g_cnt[threadIdx.x] = 0; g_cnt2[threadIdx.x] = 0; }
}

__global__ void k_router(const float* __restrict__ x, const float* __restrict__ gw,
                         float* __restrict__ out_logits) {
    const int t = blockIdx.x;
    const int tid = threadIdx.x;
    float acc[NE];
#pragma unroll
    for (int e = 0; e < NE; e++) acc[e] = 0.f;
    const float* xr = x + (size_t)t * HD;
    for (int h = tid; h < HD; h += 256) {
        float xv = xr[h];
        const float* g = gw + (size_t)h * NE;
#pragma unroll
        for (int e = 0; e < NE; e++) acc[e] += xv * g[e];
    }
    __shared__ float red[256][NE];
#pragma unroll
    for (int e = 0; e < NE; e++) red[tid][e] = acc[e];
    __syncthreads();
    for (int off = 128; off > 0; off >>= 1) {
        if (tid < off) {
#pragma unroll
            for (int e = 0; e < NE; e++) red[tid][e] += red[tid + off][e];
        }
        __syncthreads();
    }
    if (tid == 0) {
        float l[NE];
#pragma unroll
        for (int e = 0; e < NE; e++) l[e] = red[0][e];
        if (out_logits) {
#pragma unroll
            for (int e = 0; e < NE; e++) out_logits[(size_t)t * NE + e] = l[e];
        }
        int e0 = 0;
#pragma unroll
        for (int e = 1; e < NE; e++) if (l[e] > l[e0]) e0 = e;
        int e1 = -1; float l1 = -1e30f;
#pragma unroll
        for (int e = 0; e < NE; e++) if (e != e0 && l[e] > l1) { l1 = l[e]; e1 = e; }
        float d = expf(l1 - l[e0]);
        float w0 = 1.f / (1.f + d);
        g_tok_e[2*t] = e0; g_tok_e[2*t+1] = e1;
        g_tok_w[2*t] = w0; g_tok_w[2*t+1] = 1.f - w0;
        atomicAdd(&g_cnt[e0], 1);
        atomicAdd(&g_cnt[e1], 1);
    }
}

__global__ void k_offsets() {
    const int tid = threadIdx.x;
    if (tid == 0) {
        int cur = 0, mt = 0;
        for (int e = 0; e < NE; e++) {
            g_off[e] = cur;
            int tiles = (g_cnt[e] + BM - 1) / BM;
            for (int j = 0; j < tiles; j++) g_tile_e[mt++] = e;
            cur += tiles * BM;
        }
        for (; mt < MAXMT; mt++) g_tile_e[mt] = -1;
    }
    for (int i = tid; i < MAXSLOT; i += blockDim.x) g_slot_token[i] = -1;
}

__global__ void k_scatter() {
    int t = blockIdx.x * blockDim.x + threadIdx.x;
    if (t >= TN) return;
#pragma unroll
    for (int k = 0; k < NK; k++) {
        int e = g_tok_e[2*t + k];
        int pos = atomicAdd(&g_cnt2[e], 1);
        int slot = g_off[e] + pos;
        g_slot_token[slot] = t;
        g_tok_slot[2*t + k] = slot;
    }
}

// ---------------- prep: weight transpose + fp16 convert, coalesced writes ----------------
// src: [E][K][N] fp32  ->  dst rows (n-major) with stride K, fp16.
// mode 0: row = n (direct, for Wd)
// mode 1: row = (n>>3)*16 + (n&7)        (gate -> first 8 of each 16-row block)
// mode 2: row = (n>>3)*16 + (n&7) + 8    (up   -> second 8)
__global__ void k_prepw(const float* __restrict__ src, __half* __restrict__ dst,
                        int K, int N, int nrows, int mode) {
    __shared__ float s[64 * 129];
    const int e = blockIdx.z;
    const int n0 = blockIdx.x * 128, k0 = blockIdx.y * 64;
    const float* sp = src + (size_t)e * K * N + (size_t)k0 * N + n0;
#pragma unroll
    for (int i = 0; i < 8; i++) {
        int q = threadIdx.x + i * 256;           // 0..2047 float4 pieces
        int kr = q >> 5, c4 = (q & 31) * 4;
        float4 v = *(const float4*)(sp + (size_t)kr * N + c4);
        float* d = s + kr * 129 + c4;
        d[0] = v.x; d[1] = v.y; d[2] = v.z; d[3] = v.w;
    }
    __syncthreads();
    __half* dp = dst + (size_t)e * nrows * K + k0;
#pragma unroll
    for (int i = 0; i < 4; i++) {
        int j = threadIdx.x + i * 256;           // 0..1023 uint4 pieces
        int n = j >> 3, kq = (j & 7) * 8;
        uint32_t w[4];
#pragma unroll
        for (int t = 0; t < 4; t++)
            w[t] = packh2(s[(kq + 2*t) * 129 + n], s[(kq + 2*t + 1) * 129 + n]);
        int ng = n0 + n;
        size_t row;
        if (mode == 0)      row = (size_t)ng;
        else if (mode == 1) row = (size_t)(ng >> 3) * 16 + (ng & 7);
        else                row = (size_t)(ng >> 3) * 16 + (ng & 7) + 8;
        *(uint4*)(dp + row * K + kq) = *(uint4*)w;
    }
}

// ---------------- prep: gather x rows per slot -> fp16 ----------------
__global__ void k_gatherx(const float* __restrict__ x) {
    int slot = blockIdx.x;
    int t = g_slot_token[slot];
    __half* row = g_x1 + (size_t)slot * HD;
    for (int k = threadIdx.x * 2; k < HD; k += 512) {
        float v0 = 0.f, v1 = 0.f;
        if (t >= 0) {
            v0 = x[(size_t)t * HD + k];
            v1 = x[(size_t)t * HD + k + 1];
        }
        *(uint32_t*)&row[k] = packh2(v0, v1);
    }
}

// ---------------- GEMM1: x @ B' (8-col interleaved gate|up), register gelu epilogue ----------------
// grid (MAXMT, 2*ID/128=64), 256 thr, 3-stage 32KB, 2 CTAs/SM.
__global__ void __launch_bounds__(256, 2)
k_gemm1i(const __half* __restrict__ A, const __half* __restrict__ B) {
    const int mt = blockIdx.x;
    const int e = g_tile_e[mt];
    if (e < 0) return;
    const int m0 = mt * BM;
    const int nb0 = blockIdx.y * 128;            // B' row offset
    extern __shared__ char smraw[];
    const uint32_t sbase = smem_u32(smraw);
    const int tid = threadIdx.x, lane = tid & 31, wid = tid >> 5;
    const int wm = (wid >> 2) * 64, wn = (wid & 3) * 32;
    const int Kc = HD / BK;   // 32

    const int prow = tid >> 3, pkc = tid & 7;
    const uint32_t sw = ((uint32_t)(pkc ^ (prow & 7))) << 4;
    const __half* aptr = A + (size_t)(m0 + prow) * HD + pkc * 8;
    const __half* bptr = B + ((size_t)e * (2 * ID) + nb0 + prow) * HD + pkc * 8;

    auto load_stage = [&](int s, int c) {
        uint32_t d = sbase + s * STAGE;
        const __half* a = aptr + c * BK;
        const __half* b = bptr + c * BK;
#pragma unroll
        for (int t = 0; t < 4; t++) {
            uint32_t dd = d + (prow + 32*t) * 128 + sw;
            cp16(dd,          a + (size_t)(32*t) * HD);
            cp16(dd + 16384,  b + (size_t)(32*t) * HD);
        }
    };

    load_stage(0, 0); CP_COMMIT();
    load_stage(1, 1); CP_COMMIT();

    float acc[4][4][4];
#pragma unroll
    for (int i = 0; i < 4; i++)
#pragma unroll
        for (int j = 0; j < 4; j++)
#pragma unroll
            for (int q = 0; q < 4; q++) acc[i][j][q] = 0.f;

    const int lrow = lane & 15, lk = lane >> 4;

    for (int c = 0; c < Kc; c++) {
        CP_WAIT1();
        __syncthreads();
        if (c + 2 < Kc) load_stage((c + 2) % 3, c + 2);
        CP_COMMIT();
        const uint32_t sa = sbase + (c % 3) * STAGE;
#pragma unroll
        for (int ks = 0; ks < 4; ks++) {
            uint32_t ah[4][4], bf[2][4];
            const int kc = ks * 2 + lk;
#pragma unroll
            for (int mi = 0; mi < 4; mi++) {
                int row = wm + mi * 16 + lrow;
                ldsm4(ah[mi], sa + row * 128 + ((kc ^ (row & 7)) << 4));
            }
#pragma unroll
            for (int ng = 0; ng < 2; ng++) {
                int row = wn + ng * 16 + lrow;
                ldsm4(bf[ng], sa + 16384 + row * 128 + ((kc ^ (row & 7)) << 4));
            }
#pragma unroll
            for (int mi = 0; mi < 4; mi++)
#pragma unroll
                for (int nf = 0; nf < 4; nf++) {
                    const int ng = nf >> 1, p = nf & 1;
                    mmah(acc[mi][nf], ah[mi], bf[ng][p], bf[ng][p + 2]);
                }
        }
    }

    // epilogue: nf pairs (0,1) and (2,3) hold gate/up for the SAME output cols
    const int r0 = lane >> 2, c0 = (lane & 3) * 2;
    const int ob = blockIdx.y * 64 + (wn >> 1);   // warp's output col base
#pragma unroll
    for (int mi = 0; mi < 4; mi++) {
        int row = m0 + wm + mi * 16 + r0;
#pragma unroll
        for (int g = 0; g < 2; g++) {
            const float* ag = acc[mi][2*g];
            const float* au = acc[mi][2*g + 1];
            int col = ob + g * 8 + c0;
            float a0 = gelu_tanh(ag[0]) * au[0];
            float a1 = gelu_tanh(ag[1]) * au[1];
            float a2 = gelu_tanh(ag[2]) * au[2];
            float a3 = gelu_tanh(ag[3]) * au[3];
            *(uint32_t*)(g_a1 + (size_t)row * ID + col) = packh2(a0, a1);
            *(uint32_t*)(g_a1 + (size_t)(row + 8) * ID + col) = packh2(a2, a3);
        }
    }
}

// ---------------- GEMM2: y = act @ Wd (plain fp16, 3-stage, 2 CTAs/SM) ----------------
__global__ void __launch_bounds__(256, 2)
k_gemm2(const __half* __restrict__ A, const __half* __restrict__ B,
        float* __restrict__ C) {
    const int mt = blockIdx.x;
    const int e = g_tile_e[mt];
    if (e < 0) return;
    const int m0 = mt * BM;
    const int n0 = blockIdx.y * BN;
    extern __shared__ char smraw[];
    const uint32_t sbase = smem_u32(smraw);
    const int tid = threadIdx.x, lane = tid & 31, wid = tid >> 5;
    const int wm = (wid >> 2) * 64, wn = (wid & 3) * 32;
    const int Kc = ID / BK;   // 64

    const int prow = tid >> 3, pkc = tid & 7;
    const uint32_t sw = ((uint32_t)(pkc ^ (prow & 7))) << 4;
    const __half* aptr = A + (size_t)(m0 + prow) * ID + pkc * 8;
    const __half* bptr = B + ((size_t)e * HD + n0 + prow) * ID + pkc * 8;

    auto load_stage = [&](int s, int c) {
        uint32_t d = sbase + s * STAGE;
        const __half* a = aptr + c * BK;
        const __half* b = bptr + c * BK;
#pragma unroll
        for (int t = 0; t < 4; t++) {
            uint32_t dd = d + (prow + 32*t) * 128 + sw;
            cp16(dd,          a + (size_t)(32*t) * ID);
            cp16(dd + 16384,  b + (size_t)(32*t) * ID);
        }
    };

    load_stage(0, 0); CP_COMMIT();
    load_stage(1, 1); CP_COMMIT();

    float acc[4][4][4];
#pragma unroll
    for (int i = 0; i < 4; i++)
#pragma unroll
        for (int j = 0; j < 4; j++)
#pragma unroll
            for (int q = 0; q < 4; q++) acc[i][j][q] = 0.f;

    const int lrow = lane & 15, lk = lane >> 4;

    for (int c = 0; c < Kc; c++) {
        CP_WAIT1();
        __syncthreads();
        if (c + 2 < Kc) load_stage((c + 2) % 3, c + 2);
        CP_COMMIT();
        const uint32_t sa = sbase + (c % 3) * STAGE;
#pragma unroll
        for (int ks = 0; ks < 4; ks++) {
            uint32_t ah[4][4], bf[2][4];
            const int kc = ks * 2 + lk;
#pragma unroll
            for (int mi = 0; mi < 4; mi++) {
                int row = wm + mi * 16 + lrow;
                ldsm4(ah[mi], sa + row * 128 + ((kc ^ (row & 7)) << 4));
            }
#pragma unroll
            for (int ng = 0; ng < 2; ng++) {
                int row = wn + ng * 16 + lrow;
                ldsm4(bf[ng], sa + 16384 + row * 128 + ((kc ^ (row & 7)) << 4));
            }
#pragma unroll
            for (int mi = 0; mi < 4; mi++)
#pragma unroll
                for (int nf = 0; nf < 4; nf++) {
                    const int ng = nf >> 1, p = nf & 1;
                    mmah(acc[mi][nf], ah[mi], bf[ng][p], bf[ng][p + 2]);
                }
        }
    }

#pragma unroll
    for (int mi = 0; mi < 4; mi++)
#pragma unroll
        for (int nf = 0; nf < 4; nf++) {
            int row = m0 + wm + mi * 16 + (lane >> 2);
            int col = n0 + wn + nf * 8 + (lane & 3) * 2;
            float2* p0 = (float2*)&C[(size_t)row * HD + col];
            p0->x = acc[mi][nf][0]; p0->y = acc[mi][nf][1];
            float2* p1 = (float2*)&C[(size_t)(row + 8) * HD + col];
            p1->x = acc[mi][nf][2]; p1->y = acc[mi][nf][3];
        }
}

// ---------------- combine ----------------
__global__ void k_combine(float* __restrict__ out) {
    int idx = blockIdx.x * blockDim.x + threadIdx.x;
    int t = idx / (HD / 4);
    int c = (idx % (HD / 4)) * 4;
    int s0 = g_tok_slot[2*t], s1 = g_tok_slot[2*t+1];
    float w0 = g_tok_w[2*t], w1 = g_tok_w[2*t+1];
    float4 y0 = *(const float4*)&g_y[(size_t)s0 * HD + c];
    float4 y1 = *(const float4*)&g_y[(size_t)s1 * HD + c];
    float4 r;
    r.x = w0*y0.x + w1*y1.x; r.y = w0*y0.y + w1*y1.y;
    r.z = w0*y0.z + w1*y1.z; r.w = w0*y0.w + w1*y1.w;
    *(float4*)&out[(size_t)t * HD + c] = r;
}

// ---------------- host ----------------
extern "C" void kernel_launch(void* const* d_in, const int* in_sizes, int n_in,
                              void* d_out, int out_size) {
    const float* x  = (const float*)d_in[0];
    const float* gw = (const float*)d_in[1];
    const float* wg = (const float*)d_in[2];
    const float* wu = (const float*)d_in[3];
    const float* wd = (const float*)d_in[4];
    float* out = (float*)d_out;

    float* logits = nullptr;
    if ((long long)out_size >= (long long)TN * HD + (long long)TN * NE)
        logits = out + (size_t)TN * HD;

    void *p_w1, *p_wd, *p_x1, *p_a1, *p_y;
    cudaGetSymbolAddress(&p_w1, g_w1);
    cudaGetSymbolAddress(&p_wd, g_wd);
    cudaGetSymbolAddress(&p_x1, g_x1);
    cudaGetSymbolAddress(&p_a1, g_a1);
    cudaGetSymbolAddress(&p_y, g_y);

    // Streams/events created ONCE (first call = correctness run, before the
    // harness's pre-capture memory baseline). Reused on every call so no
    // device memory is allocated during or after graph capture. The enqueued
    // work is identical on every call (same topology, same kernels).
    static cudaStream_t s1 = nullptr, s2 = nullptr;
    static cudaEvent_t evRoot = nullptr, evS1 = nullptr, evS2 = nullptr;
    if (!s1) {
        cudaStreamCreateWithFlags(&s1, cudaStreamNonBlocking);
        cudaStreamCreateWithFlags(&s2, cudaStreamNonBlocking);
        cudaEventCreateWithFlags(&evRoot, cudaEventDisableTiming);
        cudaEventCreateWithFlags(&evS1, cudaEventDisableTiming);
        cudaEventCreateWithFlags(&evS2, cudaEventDisableTiming);
        cudaFuncSetAttribute(k_gemm1i, cudaFuncAttributeMaxDynamicSharedMemorySize, G_SMEM);
        cudaFuncSetAttribute(k_gemm2,  cudaFuncAttributeMaxDynamicSharedMemorySize, G_SMEM);
    }

    cudaEventRecord(evRoot, 0);
    cudaStreamWaitEvent(s1, evRoot, 0);
    cudaStreamWaitEvent(s2, evRoot, 0);

    // s1: gate/up -> fine-interleaved B' (8192 rows/expert)
    k_prepw<<<dim3(ID/128, HD/64, NE), 256, 0, s1>>>(wg, (__half*)p_w1, HD, ID, 2*ID, 1);
    k_prepw<<<dim3(ID/128, HD/64, NE), 256, 0, s1>>>(wu, (__half*)p_w1, HD, ID, 2*ID, 2);
    cudaEventRecord(evS1, s1);
    // s2: down -> direct (2048 rows/expert)
    k_prepw<<<dim3(HD/128, ID/64, NE), 256, 0, s2>>>(wd, (__half*)p_wd, ID, HD, HD, 0);
    cudaEventRecord(evS2, s2);

    // default: routing chain
    k_zero<<<1, 32>>>();
    k_router<<<TN, 256>>>(x, gw, logits);
    k_offsets<<<1, 256>>>();
    k_scatter<<<TN / 256, 256>>>();
    k_gatherx<<<MAXSLOT, 256>>>(x);

    cudaStreamWaitEvent(0, evS1, 0);
    k_gemm1i<<<dim3(MAXMT, (2*ID)/128), 256, G_SMEM>>>(
        (const __half*)p_x1, (const __half*)p_w1);
    cudaStreamWaitEvent(0, evS2, 0);
    k_gemm2<<<dim3(MAXMT, HD/BN), 256, G_SMEM>>>(
        (const __half*)p_a1, (const __half*)p_wd, (float*)p_y);
    k_combine<<<(TN * HD / 4) / 256, 256>>>(out);
}